// round 2
// baseline (speedup 1.0000x reference)
#include <cuda_runtime.h>
#include <cstdint>
#include <cstddef>

// Problem constants
#define B_   2
#define L_   2048
#define D_   1024
#define H_   16
#define HD_  64
#define BL_  (B_ * L_)        // 4096
#define NBIAS_ 257            // 2*128+1

static const size_t OUT_ELEMS = (size_t)BL_ * D_;                 // 4,194,304
static const size_t ATT_ELEMS = (size_t)B_ * H_ * L_ * (size_t)L_; // 134,217,728

// Scratch (device globals: allocation-free rule)
__device__ float g_Q[BL_ * D_];
__device__ float g_K[BL_ * D_];
__device__ float g_V[BL_ * D_];
__device__ float g_ctx[BL_ * D_];
__device__ float g_attn[(size_t)B_ * H_ * L_ * (size_t)L_]; // fallback if attn not in d_out

// ---------------------------------------------------------------------------
// Packed f32x2 helpers (FFMA2 — 2 fp32 FMAs per issue; ptxas never emits it
// from C++, only via PTX fma.rn.f32x2)
// ---------------------------------------------------------------------------
__device__ __forceinline__ unsigned long long pk2(float lo, float hi) {
    unsigned long long r;
    asm("mov.b64 %0, {%1, %2};" : "=l"(r) : "f"(lo), "f"(hi));
    return r;
}
__device__ __forceinline__ unsigned long long ffma2(unsigned long long a,
                                                    unsigned long long b,
                                                    unsigned long long c) {
    unsigned long long d;
    asm("fma.rn.f32x2 %0, %1, %2, %3;" : "=l"(d) : "l"(a), "l"(b), "l"(c));
    return d;
}
__device__ __forceinline__ float2 upk2(unsigned long long v) {
    float2 f;
    asm("mov.b64 {%0, %1}, %2;" : "=f"(f.x), "=f"(f.y) : "l"(v));
    return f;
}

// ---------------------------------------------------------------------------
// 128x128x8 register-tiled fp32 GEMM with f32x2 math:
//   C[M,N] = A[M,K] @ W[K,N] + bias
// ---------------------------------------------------------------------------
__global__ __launch_bounds__(256)
void sgemm_bias(const float* __restrict__ A, const float* __restrict__ W,
                const float* __restrict__ bias, float* __restrict__ C,
                int M, int N, int K)
{
    __shared__ float As[8][128];
    __shared__ float Bs[8][128];

    const int tid = threadIdx.x;
    const int bx = blockIdx.x;   // N tile
    const int by = blockIdx.y;   // M tile

    const int aRow = tid >> 1;          // 0..127
    const int aCol = (tid & 1) * 4;     // 0 or 4
    const int bRow = tid >> 5;          // 0..7
    const int bCol = (tid & 31) * 4;    // 0..124

    const int tx = tid & 15;            // 0..15 (cols, 8 each)
    const int ty = tid >> 4;            // 0..15 (rows, 8 each)

    const float* Ap = A + (size_t)(by * 128) * K;
    const float* Wp = W + bx * 128;

    unsigned long long acc[8][4];
#pragma unroll
    for (int i = 0; i < 8; i++)
#pragma unroll
        for (int j = 0; j < 4; j++) acc[i][j] = 0ull;

    for (int k0 = 0; k0 < K; k0 += 8) {
        float4 av = *(const float4*)(Ap + (size_t)aRow * K + k0 + aCol);
        As[aCol + 0][aRow] = av.x;
        As[aCol + 1][aRow] = av.y;
        As[aCol + 2][aRow] = av.z;
        As[aCol + 3][aRow] = av.w;
        *(float4*)&Bs[bRow][bCol] = *(const float4*)(Wp + (size_t)(k0 + bRow) * N + bCol);
        __syncthreads();
#pragma unroll
        for (int kk = 0; kk < 8; kk++) {
            float ar[8];
            unsigned long long br[4];
#pragma unroll
            for (int i = 0; i < 8; i++) ar[i] = As[kk][ty * 8 + i];
#pragma unroll
            for (int j = 0; j < 4; j++)
                br[j] = *(const unsigned long long*)&Bs[kk][tx * 8 + 2 * j];
#pragma unroll
            for (int i = 0; i < 8; i++) {
                unsigned long long a2 = pk2(ar[i], ar[i]);
#pragma unroll
                for (int j = 0; j < 4; j++) acc[i][j] = ffma2(a2, br[j], acc[i][j]);
            }
        }
        __syncthreads();
    }

    const float* bp = bias + bx * 128 + tx * 8;
    float bv[8];
#pragma unroll
    for (int j = 0; j < 8; j++) bv[j] = bp[j];
#pragma unroll
    for (int i = 0; i < 8; i++) {
        int row = by * 128 + ty * 8 + i;
        float* Cr = C + (size_t)row * N + bx * 128 + tx * 8;
        float2 p0 = upk2(acc[i][0]);
        float2 p1 = upk2(acc[i][1]);
        float2 p2 = upk2(acc[i][2]);
        float2 p3 = upk2(acc[i][3]);
        *(float4*)Cr       = make_float4(p0.x + bv[0], p0.y + bv[1], p1.x + bv[2], p1.y + bv[3]);
        *(float4*)(Cr + 4) = make_float4(p2.x + bv[4], p2.y + bv[5], p3.x + bv[6], p3.y + bv[7]);
    }
}

// ---------------------------------------------------------------------------
// Scores: S[b,h,q,k] = (Q . K)/8 + rel_bias[clip(k-q)+128, h]
// ---------------------------------------------------------------------------
__global__ __launch_bounds__(256)
void scores_kernel(const float* __restrict__ rel_bias, float* __restrict__ attn)
{
    __shared__ float As[8][128];
    __shared__ float Bs[8][128];
    __shared__ float sb[NBIAS_];

    const int tid = threadIdx.x;
    const int bx = blockIdx.x;   // k tile (of 16)
    const int by = blockIdx.y;   // q tile (of 16)
    const int bh = blockIdx.z;   // 0..31
    const int b = bh >> 4;
    const int h = bh & 15;

    for (int i = tid; i < NBIAS_; i += 256) sb[i] = rel_bias[i * H_ + h];

    const int aRow = tid >> 1;         // 0..127
    const int aCol = (tid & 1) * 4;    // 0 or 4
    const int tx = tid & 15;
    const int ty = tid >> 4;

    const float* Qb = g_Q + (size_t)(b * L_ + by * 128) * D_ + h * HD_;
    const float* Kb = g_K + (size_t)(b * L_ + bx * 128) * D_ + h * HD_;

    unsigned long long acc[8][4];
#pragma unroll
    for (int i = 0; i < 8; i++)
#pragma unroll
        for (int j = 0; j < 4; j++) acc[i][j] = 0ull;

    for (int k0 = 0; k0 < HD_; k0 += 8) {
        float4 av = *(const float4*)(Qb + (size_t)aRow * D_ + k0 + aCol);
        As[aCol + 0][aRow] = av.x;
        As[aCol + 1][aRow] = av.y;
        As[aCol + 2][aRow] = av.z;
        As[aCol + 3][aRow] = av.w;
        float4 bvv = *(const float4*)(Kb + (size_t)aRow * D_ + k0 + aCol);
        Bs[aCol + 0][aRow] = bvv.x;
        Bs[aCol + 1][aRow] = bvv.y;
        Bs[aCol + 2][aRow] = bvv.z;
        Bs[aCol + 3][aRow] = bvv.w;
        __syncthreads();
#pragma unroll
        for (int kk = 0; kk < 8; kk++) {
            float ar[8];
            unsigned long long br[4];
#pragma unroll
            for (int i = 0; i < 8; i++) ar[i] = As[kk][ty * 8 + i];
#pragma unroll
            for (int j = 0; j < 4; j++)
                br[j] = *(const unsigned long long*)&Bs[kk][tx * 8 + 2 * j];
#pragma unroll
            for (int i = 0; i < 8; i++) {
                unsigned long long a2 = pk2(ar[i], ar[i]);
#pragma unroll
                for (int j = 0; j < 4; j++) acc[i][j] = ffma2(a2, br[j], acc[i][j]);
            }
        }
        __syncthreads();
    }

    const float scale = 0.125f;   // 1/sqrt(64)
#pragma unroll
    for (int i = 0; i < 8; i++) {
        int q = by * 128 + ty * 8 + i;
        int kc0 = bx * 128 + tx * 8;
        float* out = attn + ((size_t)bh * L_ + q) * L_ + kc0;
        float vacc[8];
        float2 p0 = upk2(acc[i][0]);
        float2 p1 = upk2(acc[i][1]);
        float2 p2 = upk2(acc[i][2]);
        float2 p3 = upk2(acc[i][3]);
        vacc[0] = p0.x; vacc[1] = p0.y; vacc[2] = p1.x; vacc[3] = p1.y;
        vacc[4] = p2.x; vacc[5] = p2.y; vacc[6] = p3.x; vacc[7] = p3.y;
        float v[8];
#pragma unroll
        for (int j = 0; j < 8; j++) {
            int rel = kc0 + j - q;
            rel = rel < -128 ? -128 : (rel > 128 ? 128 : rel);
            v[j] = vacc[j] * scale + sb[rel + 128];
        }
        *(float4*)out = make_float4(v[0], v[1], v[2], v[3]);
        *(float4*)(out + 4) = make_float4(v[4], v[5], v[6], v[7]);
    }
}

// ---------------------------------------------------------------------------
// Row softmax over Lk=2048, in place. One block per row, 256 threads x 8 elems
// ---------------------------------------------------------------------------
__device__ __forceinline__ float warpMax(float v) {
#pragma unroll
    for (int o = 16; o > 0; o >>= 1) v = fmaxf(v, __shfl_xor_sync(0xffffffffu, v, o));
    return v;
}
__device__ __forceinline__ float warpSum(float v) {
#pragma unroll
    for (int o = 16; o > 0; o >>= 1) v += __shfl_xor_sync(0xffffffffu, v, o);
    return v;
}

__global__ __launch_bounds__(256)
void softmax_kernel(float* __restrict__ attn)
{
    __shared__ float sm[8];
    __shared__ float ss[8];

    const size_t row = blockIdx.x;
    float* p = attn + row * (size_t)L_;
    const int tid = threadIdx.x;
    const int lane = tid & 31;
    const int warp = tid >> 5;

    float4 v0 = ((const float4*)p)[tid];
    float4 v1 = ((const float4*)p)[tid + 256];

    float m = fmaxf(fmaxf(fmaxf(v0.x, v0.y), fmaxf(v0.z, v0.w)),
                    fmaxf(fmaxf(v1.x, v1.y), fmaxf(v1.z, v1.w)));
    m = warpMax(m);
    if (lane == 0) sm[warp] = m;
    __syncthreads();
    if (warp == 0) {
        float t = (lane < 8) ? sm[lane] : -3.4e38f;
        t = warpMax(t);
        if (lane == 0) sm[0] = t;
    }
    __syncthreads();
    m = sm[0];

    v0.x = __expf(v0.x - m); v0.y = __expf(v0.y - m);
    v0.z = __expf(v0.z - m); v0.w = __expf(v0.w - m);
    v1.x = __expf(v1.x - m); v1.y = __expf(v1.y - m);
    v1.z = __expf(v1.z - m); v1.w = __expf(v1.w - m);

    float s = (v0.x + v0.y) + (v0.z + v0.w) + (v1.x + v1.y) + (v1.z + v1.w);
    s = warpSum(s);
    if (lane == 0) ss[warp] = s;
    __syncthreads();
    if (warp == 0) {
        float t = (lane < 8) ? ss[lane] : 0.0f;
        t = warpSum(t);
        if (lane == 0) ss[0] = t;
    }
    __syncthreads();
    float inv = 1.0f / ss[0];

    v0.x *= inv; v0.y *= inv; v0.z *= inv; v0.w *= inv;
    v1.x *= inv; v1.y *= inv; v1.z *= inv; v1.w *= inv;
    ((float4*)p)[tid] = v0;
    ((float4*)p)[tid + 256] = v1;
}

// ---------------------------------------------------------------------------
// PV: ctx[b, q, h*64+d] = sum_k P[b,h,q,k] * V[b, k, h*64+d]
// 128(q) x 64(d) tiles, K-chunk 16 over Lk=2048, f32x2 math
// ---------------------------------------------------------------------------
__global__ __launch_bounds__(256)
void av_kernel(const float* __restrict__ attn)
{
    __shared__ float Ps[16][128];
    __shared__ float Vs[16][64];

    const int tid = threadIdx.x;
    const int by = blockIdx.x;   // q tile, 0..15
    const int bh = blockIdx.y;   // 0..31
    const int b = bh >> 4;
    const int h = bh & 15;

    const int pRow = tid >> 1;          // 0..127 (q)
    const int pCol = (tid & 1) * 8;     // 0 or 8 (k)
    const int vRow = tid >> 4;          // 0..15 (k)
    const int vCol = (tid & 15) * 4;    // 0..60 (d)

    const int tx = tid & 15;            // d groups of 4
    const int ty = tid >> 4;            // q groups of 8

    const float* Pb = attn + ((size_t)bh * L_ + by * 128) * L_;
    const float* Vb = g_V + (size_t)(b * L_) * D_ + h * HD_;

    unsigned long long acc[8][2];
#pragma unroll
    for (int i = 0; i < 8; i++) {
        acc[i][0] = 0ull; acc[i][1] = 0ull;
    }

    for (int k0 = 0; k0 < L_; k0 += 16) {
        float4 p0 = *(const float4*)(Pb + (size_t)pRow * L_ + k0 + pCol);
        float4 p1 = *(const float4*)(Pb + (size_t)pRow * L_ + k0 + pCol + 4);
        Ps[pCol + 0][pRow] = p0.x;
        Ps[pCol + 1][pRow] = p0.y;
        Ps[pCol + 2][pRow] = p0.z;
        Ps[pCol + 3][pRow] = p0.w;
        Ps[pCol + 4][pRow] = p1.x;
        Ps[pCol + 5][pRow] = p1.y;
        Ps[pCol + 6][pRow] = p1.z;
        Ps[pCol + 7][pRow] = p1.w;
        *(float4*)&Vs[vRow][vCol] = *(const float4*)(Vb + (size_t)(k0 + vRow) * D_ + vCol);
        __syncthreads();
#pragma unroll
        for (int kk = 0; kk < 16; kk++) {
            float ar[8];
            unsigned long long br[2];
#pragma unroll
            for (int i = 0; i < 8; i++) ar[i] = Ps[kk][ty * 8 + i];
            br[0] = *(const unsigned long long*)&Vs[kk][tx * 4];
            br[1] = *(const unsigned long long*)&Vs[kk][tx * 4 + 2];
#pragma unroll
            for (int i = 0; i < 8; i++) {
                unsigned long long a2 = pk2(ar[i], ar[i]);
                acc[i][0] = ffma2(a2, br[0], acc[i][0]);
                acc[i][1] = ffma2(a2, br[1], acc[i][1]);
            }
        }
        __syncthreads();
    }

#pragma unroll
    for (int i = 0; i < 8; i++) {
        int q = by * 128 + ty * 8 + i;
        float* out = g_ctx + (size_t)(b * L_ + q) * D_ + h * HD_ + tx * 4;
        float2 p0 = upk2(acc[i][0]);
        float2 p1 = upk2(acc[i][1]);
        *(float4*)out = make_float4(p0.x, p0.y, p1.x, p1.y);
    }
}

// ---------------------------------------------------------------------------
extern "C" void kernel_launch(void* const* d_in, const int* in_sizes, int n_in,
                              void* d_out, int out_size)
{
    const float* query = (const float*)d_in[0];
    const float* key_  = (const float*)d_in[1];
    const float* value = (const float*)d_in[2];
    const float* Wq = (const float*)d_in[3];
    const float* bq = (const float*)d_in[4];
    const float* Wk = (const float*)d_in[5];
    const float* bk = (const float*)d_in[6];
    const float* Wv = (const float*)d_in[7];
    const float* bv = (const float*)d_in[8];
    const float* Wo = (const float*)d_in[9];
    const float* bo = (const float*)d_in[10];
    const float* rel_bias = (const float*)d_in[11];
    float* outp = (float*)d_out;

    // Resolve scratch symbol addresses (not stream ops; capture-safe)
    static float *Qp = nullptr, *Kp = nullptr, *Vp = nullptr, *Cp = nullptr, *Ap = nullptr;
    if (!Qp) {
        cudaGetSymbolAddress((void**)&Qp, g_Q);
        cudaGetSymbolAddress((void**)&Kp, g_K);
        cudaGetSymbolAddress((void**)&Vp, g_V);
        cudaGetSymbolAddress((void**)&Cp, g_ctx);
        cudaGetSymbolAddress((void**)&Ap, g_attn);
    }

    // Attention matrix: second output if the harness expects it, else scratch.
    float* attn = ((size_t)out_size >= OUT_ELEMS + ATT_ELEMS) ? (outp + OUT_ELEMS) : Ap;

    dim3 gProj(D_ / 128, BL_ / 128);       // (8, 32)
    sgemm_bias<<<gProj, 256>>>(query, Wq, bq, Qp, BL_, D_, D_);
    sgemm_bias<<<gProj, 256>>>(key_,  Wk, bk, Kp, BL_, D_, D_);
    sgemm_bias<<<gProj, 256>>>(value, Wv, bv, Vp, BL_, D_, D_);

    dim3 gScores(L_ / 128, L_ / 128, B_ * H_);  // (16, 16, 32)
    scores_kernel<<<gScores, 256>>>(rel_bias, attn);

    softmax_kernel<<<(unsigned)(B_ * H_ * L_), 256>>>(attn);  // 65536 rows

    dim3 gAV(L_ / 128, B_ * H_);            // (16, 32)
    av_kernel<<<gAV, 256>>>(attn);

    sgemm_bias<<<gProj, 256>>>(Cp, Wo, bo, outp, BL_, D_, D_);
}

// round 3
// speedup vs baseline: 1.0012x; 1.0012x over previous
#include <cuda_runtime.h>
#include <cstdint>
#include <cstddef>

// Problem constants
#define B_   2
#define L_   2048
#define D_   1024
#define H_   16
#define HD_  64
#define BL_  (B_ * L_)        // 4096
#define NBIAS_ 257            // 2*128+1

static const size_t OUT_ELEMS = (size_t)BL_ * D_;                 // 4,194,304
static const size_t ATT_ELEMS = (size_t)B_ * H_ * L_ * (size_t)L_; // 134,217,728

// Scratch (device globals: allocation-free rule)
__device__ float g_Q[BL_ * D_];
__device__ float g_K[BL_ * D_];
__device__ float g_V[BL_ * D_];
__device__ float g_ctx[BL_ * D_];
__device__ float g_attn[(size_t)B_ * H_ * L_ * (size_t)L_]; // fallback if attn not in d_out

// ---------------------------------------------------------------------------
// Packed f32x2 helpers (FFMA2 — 2 fp32 FMAs per issue; ptxas never emits it
// from C++, only via PTX fma.rn.f32x2)
// ---------------------------------------------------------------------------
__device__ __forceinline__ unsigned long long pk2(float lo, float hi) {
    unsigned long long r;
    asm("mov.b64 %0, {%1, %2};" : "=l"(r) : "f"(lo), "f"(hi));
    return r;
}
__device__ __forceinline__ unsigned long long ffma2(unsigned long long a,
                                                    unsigned long long b,
                                                    unsigned long long c) {
    unsigned long long d;
    asm("fma.rn.f32x2 %0, %1, %2, %3;" : "=l"(d) : "l"(a), "l"(b), "l"(c));
    return d;
}
__device__ __forceinline__ float2 upk2(unsigned long long v) {
    float2 f;
    asm("mov.b64 {%0, %1}, %2;" : "=f"(f.x), "=f"(f.y) : "l"(v));
    return f;
}

// ---------------------------------------------------------------------------
// 128x128x8 register-tiled fp32 GEMM with f32x2 math:
//   C[M,N] = A[M,K] @ W[K,N] + bias
// ---------------------------------------------------------------------------
__global__ __launch_bounds__(256)
void sgemm_bias(const float* __restrict__ A, const float* __restrict__ W,
                const float* __restrict__ bias, float* __restrict__ C,
                int M, int N, int K)
{
    __shared__ float As[8][128];
    __shared__ float Bs[8][128];

    const int tid = threadIdx.x;
    const int bx = blockIdx.x;   // N tile
    const int by = blockIdx.y;   // M tile

    const int aRow = tid >> 1;          // 0..127
    const int aCol = (tid & 1) * 4;     // 0 or 4
    const int bRow = tid >> 5;          // 0..7
    const int bCol = (tid & 31) * 4;    // 0..124

    const int tx = tid & 15;            // 0..15 (cols, 8 each)
    const int ty = tid >> 4;            // 0..15 (rows, 8 each)

    const float* Ap = A + (size_t)(by * 128) * K;
    const float* Wp = W + bx * 128;

    unsigned long long acc[8][4];
#pragma unroll
    for (int i = 0; i < 8; i++)
#pragma unroll
        for (int j = 0; j < 4; j++) acc[i][j] = 0ull;

    for (int k0 = 0; k0 < K; k0 += 8) {
        float4 av = *(const float4*)(Ap + (size_t)aRow * K + k0 + aCol);
        As[aCol + 0][aRow] = av.x;
        As[aCol + 1][aRow] = av.y;
        As[aCol + 2][aRow] = av.z;
        As[aCol + 3][aRow] = av.w;
        *(float4*)&Bs[bRow][bCol] = *(const float4*)(Wp + (size_t)(k0 + bRow) * N + bCol);
        __syncthreads();
#pragma unroll
        for (int kk = 0; kk < 8; kk++) {
            float ar[8];
            unsigned long long br[4];
#pragma unroll
            for (int i = 0; i < 8; i++) ar[i] = As[kk][ty * 8 + i];
#pragma unroll
            for (int j = 0; j < 4; j++)
                br[j] = *(const unsigned long long*)&Bs[kk][tx * 8 + 2 * j];
#pragma unroll
            for (int i = 0; i < 8; i++) {
                unsigned long long a2 = pk2(ar[i], ar[i]);
#pragma unroll
                for (int j = 0; j < 4; j++) acc[i][j] = ffma2(a2, br[j], acc[i][j]);
            }
        }
        __syncthreads();
    }

    const float* bp = bias + bx * 128 + tx * 8;
    float bv[8];
#pragma unroll
    for (int j = 0; j < 8; j++) bv[j] = bp[j];
#pragma unroll
    for (int i = 0; i < 8; i++) {
        int row = by * 128 + ty * 8 + i;
        float* Cr = C + (size_t)row * N + bx * 128 + tx * 8;
        float2 p0 = upk2(acc[i][0]);
        float2 p1 = upk2(acc[i][1]);
        float2 p2 = upk2(acc[i][2]);
        float2 p3 = upk2(acc[i][3]);
        *(float4*)Cr       = make_float4(p0.x + bv[0], p0.y + bv[1], p1.x + bv[2], p1.y + bv[3]);
        *(float4*)(Cr + 4) = make_float4(p2.x + bv[4], p2.y + bv[5], p3.x + bv[6], p3.y + bv[7]);
    }
}

// ---------------------------------------------------------------------------
// Scores: S[b,h,q,k] = (Q . K)/8 + rel_bias[clip(k-q)+128, h]
// ---------------------------------------------------------------------------
__global__ __launch_bounds__(256)
void scores_kernel(const float* __restrict__ rel_bias, float* __restrict__ attn)
{
    __shared__ float As[8][128];
    __shared__ float Bs[8][128];
    __shared__ float sb[NBIAS_];

    const int tid = threadIdx.x;
    const int bx = blockIdx.x;   // k tile (of 16)
    const int by = blockIdx.y;   // q tile (of 16)
    const int bh = blockIdx.z;   // 0..31
    const int b = bh >> 4;
    const int h = bh & 15;

    for (int i = tid; i < NBIAS_; i += 256) sb[i] = rel_bias[i * H_ + h];

    const int aRow = tid >> 1;         // 0..127
    const int aCol = (tid & 1) * 4;    // 0 or 4
    const int tx = tid & 15;
    const int ty = tid >> 4;

    const float* Qb = g_Q + (size_t)(b * L_ + by * 128) * D_ + h * HD_;
    const float* Kb = g_K + (size_t)(b * L_ + bx * 128) * D_ + h * HD_;

    unsigned long long acc[8][4];
#pragma unroll
    for (int i = 0; i < 8; i++)
#pragma unroll
        for (int j = 0; j < 4; j++) acc[i][j] = 0ull;

    for (int k0 = 0; k0 < HD_; k0 += 8) {
        float4 av = *(const float4*)(Qb + (size_t)aRow * D_ + k0 + aCol);
        As[aCol + 0][aRow] = av.x;
        As[aCol + 1][aRow] = av.y;
        As[aCol + 2][aRow] = av.z;
        As[aCol + 3][aRow] = av.w;
        float4 bvv = *(const float4*)(Kb + (size_t)aRow * D_ + k0 + aCol);
        Bs[aCol + 0][aRow] = bvv.x;
        Bs[aCol + 1][aRow] = bvv.y;
        Bs[aCol + 2][aRow] = bvv.z;
        Bs[aCol + 3][aRow] = bvv.w;
        __syncthreads();
#pragma unroll
        for (int kk = 0; kk < 8; kk++) {
            float ar[8];
            unsigned long long br[4];
#pragma unroll
            for (int i = 0; i < 8; i++) ar[i] = As[kk][ty * 8 + i];
#pragma unroll
            for (int j = 0; j < 4; j++)
                br[j] = *(const unsigned long long*)&Bs[kk][tx * 8 + 2 * j];
#pragma unroll
            for (int i = 0; i < 8; i++) {
                unsigned long long a2 = pk2(ar[i], ar[i]);
#pragma unroll
                for (int j = 0; j < 4; j++) acc[i][j] = ffma2(a2, br[j], acc[i][j]);
            }
        }
        __syncthreads();
    }

    const float scale = 0.125f;   // 1/sqrt(64)
#pragma unroll
    for (int i = 0; i < 8; i++) {
        int q = by * 128 + ty * 8 + i;
        int kc0 = bx * 128 + tx * 8;
        float* out = attn + ((size_t)bh * L_ + q) * L_ + kc0;
        float vacc[8];
        float2 p0 = upk2(acc[i][0]);
        float2 p1 = upk2(acc[i][1]);
        float2 p2 = upk2(acc[i][2]);
        float2 p3 = upk2(acc[i][3]);
        vacc[0] = p0.x; vacc[1] = p0.y; vacc[2] = p1.x; vacc[3] = p1.y;
        vacc[4] = p2.x; vacc[5] = p2.y; vacc[6] = p3.x; vacc[7] = p3.y;
        float v[8];
#pragma unroll
        for (int j = 0; j < 8; j++) {
            int rel = kc0 + j - q;
            rel = rel < -128 ? -128 : (rel > 128 ? 128 : rel);
            v[j] = vacc[j] * scale + sb[rel + 128];
        }
        *(float4*)out = make_float4(v[0], v[1], v[2], v[3]);
        *(float4*)(out + 4) = make_float4(v[4], v[5], v[6], v[7]);
    }
}

// ---------------------------------------------------------------------------
// Row softmax over Lk=2048, in place. One block per row, 256 threads x 8 elems
// ---------------------------------------------------------------------------
__device__ __forceinline__ float warpMax(float v) {
#pragma unroll
    for (int o = 16; o > 0; o >>= 1) v = fmaxf(v, __shfl_xor_sync(0xffffffffu, v, o));
    return v;
}
__device__ __forceinline__ float warpSum(float v) {
#pragma unroll
    for (int o = 16; o > 0; o >>= 1) v += __shfl_xor_sync(0xffffffffu, v, o);
    return v;
}

__global__ __launch_bounds__(256)
void softmax_kernel(float* __restrict__ attn)
{
    __shared__ float sm[8];
    __shared__ float ss[8];

    const size_t row = blockIdx.x;
    float* p = attn + row * (size_t)L_;
    const int tid = threadIdx.x;
    const int lane = tid & 31;
    const int warp = tid >> 5;

    float4 v0 = ((const float4*)p)[tid];
    float4 v1 = ((const float4*)p)[tid + 256];

    float m = fmaxf(fmaxf(fmaxf(v0.x, v0.y), fmaxf(v0.z, v0.w)),
                    fmaxf(fmaxf(v1.x, v1.y), fmaxf(v1.z, v1.w)));
    m = warpMax(m);
    if (lane == 0) sm[warp] = m;
    __syncthreads();
    if (warp == 0) {
        float t = (lane < 8) ? sm[lane] : -3.4e38f;
        t = warpMax(t);
        if (lane == 0) sm[0] = t;
    }
    __syncthreads();
    m = sm[0];

    v0.x = __expf(v0.x - m); v0.y = __expf(v0.y - m);
    v0.z = __expf(v0.z - m); v0.w = __expf(v0.w - m);
    v1.x = __expf(v1.x - m); v1.y = __expf(v1.y - m);
    v1.z = __expf(v1.z - m); v1.w = __expf(v1.w - m);

    float s = (v0.x + v0.y) + (v0.z + v0.w) + (v1.x + v1.y) + (v1.z + v1.w);
    s = warpSum(s);
    if (lane == 0) ss[warp] = s;
    __syncthreads();
    if (warp == 0) {
        float t = (lane < 8) ? ss[lane] : 0.0f;
        t = warpSum(t);
        if (lane == 0) ss[0] = t;
    }
    __syncthreads();
    float inv = 1.0f / ss[0];

    v0.x *= inv; v0.y *= inv; v0.z *= inv; v0.w *= inv;
    v1.x *= inv; v1.y *= inv; v1.z *= inv; v1.w *= inv;
    ((float4*)p)[tid] = v0;
    ((float4*)p)[tid + 256] = v1;
}

// ---------------------------------------------------------------------------
// PV: ctx[b, q, h*64+d] = sum_k P[b,h,q,k] * V[b, k, h*64+d]
// 128(q) x 64(d) tiles, K-chunk 16 over Lk=2048, f32x2 math
// ---------------------------------------------------------------------------
__global__ __launch_bounds__(256)
void av_kernel(const float* __restrict__ attn)
{
    __shared__ float Ps[16][128];
    __shared__ float Vs[16][64];

    const int tid = threadIdx.x;
    const int by = blockIdx.x;   // q tile, 0..15
    const int bh = blockIdx.y;   // 0..31
    const int b = bh >> 4;
    const int h = bh & 15;

    const int pRow = tid >> 1;          // 0..127 (q)
    const int pCol = (tid & 1) * 8;     // 0 or 8 (k)
    const int vRow = tid >> 4;          // 0..15 (k)
    const int vCol = (tid & 15) * 4;    // 0..60 (d)

    const int tx = tid & 15;            // d groups of 4
    const int ty = tid >> 4;            // q groups of 8

    const float* Pb = attn + ((size_t)bh * L_ + by * 128) * L_;
    const float* Vb = g_V + (size_t)(b * L_) * D_ + h * HD_;

    unsigned long long acc[8][2];
#pragma unroll
    for (int i = 0; i < 8; i++) {
        acc[i][0] = 0ull; acc[i][1] = 0ull;
    }

    for (int k0 = 0; k0 < L_; k0 += 16) {
        float4 p0 = *(const float4*)(Pb + (size_t)pRow * L_ + k0 + pCol);
        float4 p1 = *(const float4*)(Pb + (size_t)pRow * L_ + k0 + pCol + 4);
        Ps[pCol + 0][pRow] = p0.x;
        Ps[pCol + 1][pRow] = p0.y;
        Ps[pCol + 2][pRow] = p0.z;
        Ps[pCol + 3][pRow] = p0.w;
        Ps[pCol + 4][pRow] = p1.x;
        Ps[pCol + 5][pRow] = p1.y;
        Ps[pCol + 6][pRow] = p1.z;
        Ps[pCol + 7][pRow] = p1.w;
        *(float4*)&Vs[vRow][vCol] = *(const float4*)(Vb + (size_t)(k0 + vRow) * D_ + vCol);
        __syncthreads();
#pragma unroll
        for (int kk = 0; kk < 16; kk++) {
            float ar[8];
            unsigned long long br[2];
#pragma unroll
            for (int i = 0; i < 8; i++) ar[i] = Ps[kk][ty * 8 + i];
            br[0] = *(const unsigned long long*)&Vs[kk][tx * 4];
            br[1] = *(const unsigned long long*)&Vs[kk][tx * 4 + 2];
#pragma unroll
            for (int i = 0; i < 8; i++) {
                unsigned long long a2 = pk2(ar[i], ar[i]);
                acc[i][0] = ffma2(a2, br[0], acc[i][0]);
                acc[i][1] = ffma2(a2, br[1], acc[i][1]);
            }
        }
        __syncthreads();
    }

#pragma unroll
    for (int i = 0; i < 8; i++) {
        int q = by * 128 + ty * 8 + i;
        float* out = g_ctx + (size_t)(b * L_ + q) * D_ + h * HD_ + tx * 4;
        float2 p0 = upk2(acc[i][0]);
        float2 p1 = upk2(acc[i][1]);
        *(float4*)out = make_float4(p0.x, p0.y, p1.x, p1.y);
    }
}

// ---------------------------------------------------------------------------
extern "C" void kernel_launch(void* const* d_in, const int* in_sizes, int n_in,
                              void* d_out, int out_size)
{
    const float* query = (const float*)d_in[0];
    const float* key_  = (const float*)d_in[1];
    const float* value = (const float*)d_in[2];
    const float* Wq = (const float*)d_in[3];
    const float* bq = (const float*)d_in[4];
    const float* Wk = (const float*)d_in[5];
    const float* bk = (const float*)d_in[6];
    const float* Wv = (const float*)d_in[7];
    const float* bv = (const float*)d_in[8];
    const float* Wo = (const float*)d_in[9];
    const float* bo = (const float*)d_in[10];
    const float* rel_bias = (const float*)d_in[11];
    float* outp = (float*)d_out;

    // Resolve scratch symbol addresses (not stream ops; capture-safe)
    static float *Qp = nullptr, *Kp = nullptr, *Vp = nullptr, *Cp = nullptr, *Ap = nullptr;
    if (!Qp) {
        cudaGetSymbolAddress((void**)&Qp, g_Q);
        cudaGetSymbolAddress((void**)&Kp, g_K);
        cudaGetSymbolAddress((void**)&Vp, g_V);
        cudaGetSymbolAddress((void**)&Cp, g_ctx);
        cudaGetSymbolAddress((void**)&Ap, g_attn);
    }

    // Attention matrix: second output if the harness expects it, else scratch.
    float* attn = ((size_t)out_size >= OUT_ELEMS + ATT_ELEMS) ? (outp + OUT_ELEMS) : Ap;

    dim3 gProj(D_ / 128, BL_ / 128);       // (8, 32)
    sgemm_bias<<<gProj, 256>>>(query, Wq, bq, Qp, BL_, D_, D_);
    sgemm_bias<<<gProj, 256>>>(key_,  Wk, bk, Kp, BL_, D_, D_);
    sgemm_bias<<<gProj, 256>>>(value, Wv, bv, Vp, BL_, D_, D_);

    dim3 gScores(L_ / 128, L_ / 128, B_ * H_);  // (16, 16, 32)
    scores_kernel<<<gScores, 256>>>(rel_bias, attn);

    softmax_kernel<<<(unsigned)(B_ * H_ * L_), 256>>>(attn);  // 65536 rows

    dim3 gAV(L_ / 128, B_ * H_);            // (16, 32)
    av_kernel<<<gAV, 256>>>(attn);

    sgemm_bias<<<gProj, 256>>>(Cp, Wo, bo, outp, BL_, D_, D_);
}

// round 5
// speedup vs baseline: 1.3085x; 1.3069x over previous
#include <cuda_runtime.h>
#include <cuda_fp16.h>
#include <cstdint>
#include <cstddef>

#define B_   2
#define L_   2048
#define D_   1024
#define H_   16
#define HD_  64
#define BL_  (B_ * L_)
#define NBIAS_ 257
#define STR  40   // smem row stride in halfs (80B): conflict-free for ldmatrix

static const size_t OUT_ELEMS = (size_t)BL_ * D_;
static const size_t ATT_ELEMS = (size_t)B_ * H_ * L_ * (size_t)L_;

// Device-global scratch (allocation-free rule)
__device__ float  g_Q[(size_t)BL_ * D_];
__device__ float  g_K[(size_t)BL_ * D_];
__device__ float  g_V[(size_t)BL_ * D_];
__device__ float  g_ctx[(size_t)BL_ * D_];
__device__ __half g_Wth[4ull * D_ * D_];   // transposed weights [n][k], hi part
__device__ __half g_Wtl[4ull * D_ * D_];   // lo part
__device__ __half g_Vth[(size_t)BL_ * D_]; // V transposed: [(b*16+h)*64+d][tok]
__device__ __half g_Vtl[(size_t)BL_ * D_];
__device__ float  g_attn[(size_t)B_ * H_ * L_ * (size_t)L_];

// ---------------------------------------------------------------------------
// MMA / ldmatrix helpers
// ---------------------------------------------------------------------------
__device__ __forceinline__ uint32_t smem_u32(const void* p) {
    uint32_t a;
    asm("{ .reg .u64 t; cvta.to.shared.u64 t, %1; cvt.u32.u64 %0, t; }" : "=r"(a) : "l"(p));
    return a;
}
__device__ __forceinline__ void ldsm4(uint32_t r[4], uint32_t addr) {
    asm volatile("ldmatrix.sync.aligned.m8n8.x4.shared.b16 {%0,%1,%2,%3}, [%4];"
                 : "=r"(r[0]), "=r"(r[1]), "=r"(r[2]), "=r"(r[3]) : "r"(addr));
}
__device__ __forceinline__ void ldsm2(uint32_t r[2], uint32_t addr) {
    asm volatile("ldmatrix.sync.aligned.m8n8.x2.shared.b16 {%0,%1}, [%2];"
                 : "=r"(r[0]), "=r"(r[1]) : "r"(addr));
}
__device__ __forceinline__ void mma16816(float c[4], const uint32_t a[4], const uint32_t b[2]) {
    asm volatile("mma.sync.aligned.m16n8k16.row.col.f32.f16.f16.f32 "
                 "{%0,%1,%2,%3}, {%4,%5,%6,%7}, {%8,%9}, {%0,%1,%2,%3};"
                 : "+f"(c[0]), "+f"(c[1]), "+f"(c[2]), "+f"(c[3])
                 : "r"(a[0]), "r"(a[1]), "r"(a[2]), "r"(a[3]), "r"(b[0]), "r"(b[1]));
}

__device__ __forceinline__ uint32_t h2u(__half2 v) { return *reinterpret_cast<uint32_t*>(&v); }

__device__ __forceinline__ void split4(float4 v, uint2& hi, uint2& lo) {
    __half h0 = __float2half_rn(v.x), h1 = __float2half_rn(v.y);
    __half h2 = __float2half_rn(v.z), h3 = __float2half_rn(v.w);
    __half l0 = __float2half_rn(v.x - __half2float(h0));
    __half l1 = __float2half_rn(v.y - __half2float(h1));
    __half l2 = __float2half_rn(v.z - __half2float(h2));
    __half l3 = __float2half_rn(v.w - __half2float(h3));
    hi.x = h2u(__halves2half2(h0, h1)); hi.y = h2u(__halves2half2(h2, h3));
    lo.x = h2u(__halves2half2(l0, l1)); lo.y = h2u(__halves2half2(l2, l3));
}

// Load fp32 tile [rows][32] (row stride gs floats) -> split hi/lo smem planes
__device__ __forceinline__ void ld_splitA(const float* __restrict__ g, int gs,
                                          __half* __restrict__ sh, __half* __restrict__ sl,
                                          int tid, int rows) {
    int c = tid & 7, r0 = tid >> 3;
    for (int r = r0; r < rows; r += 32) {
        float4 v = *(const float4*)(g + (size_t)r * gs + c * 4);
        uint2 hi, lo;
        split4(v, hi, lo);
        *(uint2*)(sh + r * STR + c * 4) = hi;
        *(uint2*)(sl + r * STR + c * 4) = lo;
    }
}
// Load half tile [rows][32] (row stride gs halfs) -> smem
__device__ __forceinline__ void ld_half(const __half* __restrict__ g, int gs,
                                        __half* __restrict__ s, int tid, int rows) {
    int c = tid & 3, r0 = tid >> 2;
    for (int r = r0; r < rows; r += 64) {
        uint4 v = *(const uint4*)(g + (size_t)r * gs + c * 8);
        *(uint4*)(s + r * STR + c * 8) = v;
    }
}

// ---------------------------------------------------------------------------
// Prep kernels: W[k][n] -> Wt[n][k] split;  V[tok][f] -> Vt[(b,h,d)][tok] split
// ---------------------------------------------------------------------------
__global__ void wsplit(const float* __restrict__ W, __half* __restrict__ Th,
                       __half* __restrict__ Tl) {
    __shared__ float t[32][33];
    int bx = blockIdx.x * 32, by = blockIdx.y * 32;
    int tx = threadIdx.x, ty = threadIdx.y;
    for (int i = ty; i < 32; i += 8)
        t[i][tx] = W[(size_t)(by + i) * D_ + bx + tx];
    __syncthreads();
    for (int i = ty; i < 32; i += 8) {
        float v = t[tx][i];   // W[k=by+tx][n=bx+i]
        __half h = __float2half_rn(v);
        Th[(size_t)(bx + i) * D_ + by + tx] = h;
        Tl[(size_t)(bx + i) * D_ + by + tx] = __float2half_rn(v - __half2float(h));
    }
}
__global__ void vsplit(const float* __restrict__ V, __half* __restrict__ Th,
                       __half* __restrict__ Tl) {
    __shared__ float t[32][33];
    int bx = blockIdx.x * 32, by = blockIdx.y * 32;  // bx: feat, by: tok
    int tx = threadIdx.x, ty = threadIdx.y;
    for (int i = ty; i < 32; i += 8)
        t[i][tx] = V[(size_t)(by + i) * D_ + bx + tx];
    __syncthreads();
    int tok = by + tx;
    int b = tok >> 11, tokin = tok & (L_ - 1);
    for (int i = ty; i < 32; i += 8) {
        int f = bx + i;
        float v = t[tx][i];   // V[tok][f]
        size_t row = ((size_t)(b * H_ + (f >> 6))) * 64 + (f & 63);
        __half h = __float2half_rn(v);
        Th[row * L_ + tokin] = h;
        Tl[row * L_ + tokin] = __float2half_rn(v - __half2float(h));
    }
}

// ---------------------------------------------------------------------------
// Projection GEMM: C[m][n] = A[m][:] @ W[:][n] + bias.  M=4096, N=1024, K=1024
// Block 128x128, 8 warps (2m x 4n), warp tile 64x32, 3-product fp16 split MMA.
// ---------------------------------------------------------------------------
__global__ __launch_bounds__(256) void proj_tc(
    const float* __restrict__ A32,
    const __half* __restrict__ Bth, const __half* __restrict__ Btl,
    const float* __restrict__ bias, float* __restrict__ C32)
{
    __shared__ __half sAh[128 * STR], sAl[128 * STR];
    __shared__ __half sBh[128 * STR], sBl[128 * STR];

    const int tid = threadIdx.x, wid = tid >> 5, lane = tid & 31;
    const int wm = wid >> 2, wn = wid & 3;
    const int n0 = blockIdx.x * 128, m0 = blockIdx.y * 128;

    const uint32_t pAh = smem_u32(sAh), pAl = smem_u32(sAl);
    const uint32_t pBh = smem_u32(sBh), pBl = smem_u32(sBl);

    float acc[4][4][4];
#pragma unroll
    for (int i = 0; i < 4; i++)
#pragma unroll
        for (int j = 0; j < 4; j++)
#pragma unroll
            for (int f = 0; f < 4; f++) acc[i][j][f] = 0.0f;

    for (int kt = 0; kt < D_; kt += 32) {
        ld_splitA(A32 + (size_t)m0 * D_ + kt, D_, sAh, sAl, tid, 128);
        ld_half(Bth + (size_t)n0 * D_ + kt, D_, sBh, tid, 128);
        ld_half(Btl + (size_t)n0 * D_ + kt, D_, sBl, tid, 128);
        __syncthreads();
#pragma unroll
        for (int ks = 0; ks < 32; ks += 16) {
            uint32_t ah[4][4], al[4][4], bh[4][2], bl[4][2];
            const uint32_t aoff = (uint32_t)((wm * 64 + (lane & 15)) * STR + ks + (lane >> 4) * 8) * 2;
            const uint32_t boff = (uint32_t)((wn * 32 + (lane & 7)) * STR + ks + ((lane >> 3) & 1) * 8) * 2;
#pragma unroll
            for (int mi = 0; mi < 4; mi++) {
                ldsm4(ah[mi], pAh + aoff + mi * 16 * STR * 2);
                ldsm4(al[mi], pAl + aoff + mi * 16 * STR * 2);
            }
#pragma unroll
            for (int ni = 0; ni < 4; ni++) {
                ldsm2(bh[ni], pBh + boff + ni * 8 * STR * 2);
                ldsm2(bl[ni], pBl + boff + ni * 8 * STR * 2);
            }
#pragma unroll
            for (int mi = 0; mi < 4; mi++)
#pragma unroll
                for (int ni = 0; ni < 4; ni++) {
                    mma16816(acc[mi][ni], ah[mi], bh[ni]);
                    mma16816(acc[mi][ni], ah[mi], bl[ni]);
                    mma16816(acc[mi][ni], al[mi], bh[ni]);
                }
        }
        __syncthreads();
    }

#pragma unroll
    for (int mi = 0; mi < 4; mi++)
#pragma unroll
        for (int ni = 0; ni < 4; ni++) {
            int r = m0 + wm * 64 + mi * 16 + (lane >> 2);
            int cc = n0 + wn * 32 + ni * 8 + (lane & 3) * 2;
            float b0 = bias[cc], b1 = bias[cc + 1];
            *(float2*)(C32 + (size_t)r * D_ + cc) =
                make_float2(acc[mi][ni][0] + b0, acc[mi][ni][1] + b1);
            *(float2*)(C32 + (size_t)(r + 8) * D_ + cc) =
                make_float2(acc[mi][ni][2] + b0, acc[mi][ni][3] + b1);
        }
}

// ---------------------------------------------------------------------------
// Scores: S[b,h,q,k] = (Q.K)/8 + rel_bias.  Block 128q x 128k, Kdim=64.
// ---------------------------------------------------------------------------
__global__ __launch_bounds__(256) void scores_tc(
    const float* __restrict__ rel_bias, float* __restrict__ attn)
{
    __shared__ __half sAh[128 * STR], sAl[128 * STR];
    __shared__ __half sBh[128 * STR], sBl[128 * STR];
    __shared__ float sbias[NBIAS_];

    const int tid = threadIdx.x, wid = tid >> 5, lane = tid & 31;
    const int wm = wid >> 2, wn = wid & 3;
    const int bx = blockIdx.x, by = blockIdx.y, bh_ = blockIdx.z;
    const int b = bh_ >> 4, h = bh_ & 15;

    for (int i = tid; i < NBIAS_; i += 256) sbias[i] = rel_bias[i * H_ + h];

    const uint32_t pAh = smem_u32(sAh), pAl = smem_u32(sAl);
    const uint32_t pBh = smem_u32(sBh), pBl = smem_u32(sBl);

    const float* Qb = g_Q + (size_t)(b * L_ + by * 128) * D_ + h * HD_;
    const float* Kb = g_K + (size_t)(b * L_ + bx * 128) * D_ + h * HD_;

    float acc[4][4][4];
#pragma unroll
    for (int i = 0; i < 4; i++)
#pragma unroll
        for (int j = 0; j < 4; j++)
#pragma unroll
            for (int f = 0; f < 4; f++) acc[i][j][f] = 0.0f;

    for (int kt = 0; kt < HD_; kt += 32) {
        ld_splitA(Qb + kt, D_, sAh, sAl, tid, 128);
        ld_splitA(Kb + kt, D_, sBh, sBl, tid, 128);
        __syncthreads();
#pragma unroll
        for (int ks = 0; ks < 32; ks += 16) {
            uint32_t ah[4][4], al[4][4], bh[4][2], bl[4][2];
            const uint32_t aoff = (uint32_t)((wm * 64 + (lane & 15)) * STR + ks + (lane >> 4) * 8) * 2;
            const uint32_t boff = (uint32_t)((wn * 32 + (lane & 7)) * STR + ks + ((lane >> 3) & 1) * 8) * 2;
#pragma unroll
            for (int mi = 0; mi < 4; mi++) {
                ldsm4(ah[mi], pAh + aoff + mi * 16 * STR * 2);
                ldsm4(al[mi], pAl + aoff + mi * 16 * STR * 2);
            }
#pragma unroll
            for (int ni = 0; ni < 4; ni++) {
                ldsm2(bh[ni], pBh + boff + ni * 8 * STR * 2);
                ldsm2(bl[ni], pBl + boff + ni * 8 * STR * 2);
            }
#pragma unroll
            for (int mi = 0; mi < 4; mi++)
#pragma unroll
                for (int ni = 0; ni < 4; ni++) {
                    mma16816(acc[mi][ni], ah[mi], bh[ni]);
                    mma16816(acc[mi][ni], ah[mi], bl[ni]);
                    mma16816(acc[mi][ni], al[mi], bh[ni]);
                }
        }
        __syncthreads();
    }

    float* base = attn + (size_t)bh_ * L_ * L_;
#pragma unroll
    for (int mi = 0; mi < 4; mi++)
#pragma unroll
        for (int ni = 0; ni < 4; ni++) {
            int q0 = by * 128 + wm * 64 + mi * 16 + (lane >> 2);
            int kc = bx * 128 + wn * 32 + ni * 8 + (lane & 3) * 2;
#pragma unroll
            for (int half_ = 0; half_ < 2; half_++) {
                int q = q0 + half_ * 8;
                int rel0 = kc - q;     rel0 = rel0 < -128 ? -128 : (rel0 > 128 ? 128 : rel0);
                int rel1 = kc + 1 - q; rel1 = rel1 < -128 ? -128 : (rel1 > 128 ? 128 : rel1);
                float2 o = make_float2(
                    acc[mi][ni][half_ * 2 + 0] * 0.125f + sbias[rel0 + 128],
                    acc[mi][ni][half_ * 2 + 1] * 0.125f + sbias[rel1 + 128]);
                *(float2*)(base + (size_t)q * L_ + kc) = o;
            }
        }
}

// ---------------------------------------------------------------------------
// Row softmax over Lk=2048, in place.
// ---------------------------------------------------------------------------
__device__ __forceinline__ float warpMax(float v) {
#pragma unroll
    for (int o = 16; o > 0; o >>= 1) v = fmaxf(v, __shfl_xor_sync(0xffffffffu, v, o));
    return v;
}
__device__ __forceinline__ float warpSum(float v) {
#pragma unroll
    for (int o = 16; o > 0; o >>= 1) v += __shfl_xor_sync(0xffffffffu, v, o);
    return v;
}
__global__ __launch_bounds__(256)
void softmax_kernel(float* __restrict__ attn)
{
    __shared__ float sm[8];
    __shared__ float ss[8];
    const size_t row = blockIdx.x;
    float* p = attn + row * (size_t)L_;
    const int tid = threadIdx.x, lane = tid & 31, warp = tid >> 5;

    float4 v0 = ((const float4*)p)[tid];
    float4 v1 = ((const float4*)p)[tid + 256];
    float m = fmaxf(fmaxf(fmaxf(v0.x, v0.y), fmaxf(v0.z, v0.w)),
                    fmaxf(fmaxf(v1.x, v1.y), fmaxf(v1.z, v1.w)));
    m = warpMax(m);
    if (lane == 0) sm[warp] = m;
    __syncthreads();
    if (warp == 0) {
        float t = (lane < 8) ? sm[lane] : -3.4e38f;
        t = warpMax(t);
        if (lane == 0) sm[0] = t;
    }
    __syncthreads();
    m = sm[0];
    v0.x = __expf(v0.x - m); v0.y = __expf(v0.y - m);
    v0.z = __expf(v0.z - m); v0.w = __expf(v0.w - m);
    v1.x = __expf(v1.x - m); v1.y = __expf(v1.y - m);
    v1.z = __expf(v1.z - m); v1.w = __expf(v1.w - m);
    float s = (v0.x + v0.y) + (v0.z + v0.w) + (v1.x + v1.y) + (v1.z + v1.w);
    s = warpSum(s);
    if (lane == 0) ss[warp] = s;
    __syncthreads();
    if (warp == 0) {
        float t = (lane < 8) ? ss[lane] : 0.0f;
        t = warpSum(t);
        if (lane == 0) ss[0] = t;
    }
    __syncthreads();
    float inv = 1.0f / ss[0];
    v0.x *= inv; v0.y *= inv; v0.z *= inv; v0.w *= inv;
    v1.x *= inv; v1.y *= inv; v1.z *= inv; v1.w *= inv;
    ((float4*)p)[tid] = v0;
    ((float4*)p)[tid + 256] = v1;
}

// ---------------------------------------------------------------------------
// AV: ctx[tok][h*64+d] = sum_k P[q][k] * Vt[d][k].  Block 128q x 64d, K=2048.
// 8 warps (2m x 4n), warp tile 64x16.
// ---------------------------------------------------------------------------
__global__ __launch_bounds__(256) void av_tc(const float* __restrict__ attn)
{
    __shared__ __half sAh[128 * STR], sAl[128 * STR];
    __shared__ __half sBh[64 * STR], sBl[64 * STR];

    const int tid = threadIdx.x, wid = tid >> 5, lane = tid & 31;
    const int wm = wid >> 2, wn = wid & 3;
    const int by = blockIdx.x, bh_ = blockIdx.y;
    const int b = bh_ >> 4, h = bh_ & 15;

    const uint32_t pAh = smem_u32(sAh), pAl = smem_u32(sAl);
    const uint32_t pBh = smem_u32(sBh), pBl = smem_u32(sBl);

    const float*  Pb  = attn + ((size_t)bh_ * L_ + by * 128) * L_;
    const __half* Vbh = g_Vth + (size_t)bh_ * 64 * L_;
    const __half* Vbl = g_Vtl + (size_t)bh_ * 64 * L_;

    float acc[4][2][4];
#pragma unroll
    for (int i = 0; i < 4; i++)
#pragma unroll
        for (int j = 0; j < 2; j++)
#pragma unroll
            for (int f = 0; f < 4; f++) acc[i][j][f] = 0.0f;

    for (int kt = 0; kt < L_; kt += 32) {
        ld_splitA(Pb + kt, L_, sAh, sAl, tid, 128);
        ld_half(Vbh + kt, L_, sBh, tid, 64);
        ld_half(Vbl + kt, L_, sBl, tid, 64);
        __syncthreads();
#pragma unroll
        for (int ks = 0; ks < 32; ks += 16) {
            uint32_t ah[4][4], al[4][4], bh[2][2], bl[2][2];
            const uint32_t aoff = (uint32_t)((wm * 64 + (lane & 15)) * STR + ks + (lane >> 4) * 8) * 2;
            const uint32_t boff = (uint32_t)((wn * 16 + (lane & 7)) * STR + ks + ((lane >> 3) & 1) * 8) * 2;
#pragma unroll
            for (int mi = 0; mi < 4; mi++) {
                ldsm4(ah[mi], pAh + aoff + mi * 16 * STR * 2);
                ldsm4(al[mi], pAl + aoff + mi * 16 * STR * 2);
            }
#pragma unroll
            for (int ni = 0; ni < 2; ni++) {
                ldsm2(bh[ni], pBh + boff + ni * 8 * STR * 2);
                ldsm2(bl[ni], pBl + boff + ni * 8 * STR * 2);
            }
#pragma unroll
            for (int mi = 0; mi < 4; mi++)
#pragma unroll
                for (int ni = 0; ni < 2; ni++) {
                    mma16816(acc[mi][ni], ah[mi], bh[ni]);
                    mma16816(acc[mi][ni], ah[mi], bl[ni]);
                    mma16816(acc[mi][ni], al[mi], bh[ni]);
                }
        }
        __syncthreads();
    }

#pragma unroll
    for (int mi = 0; mi < 4; mi++)
#pragma unroll
        for (int ni = 0; ni < 2; ni++) {
            int tok = b * L_ + by * 128 + wm * 64 + mi * 16 + (lane >> 2);
            int cc = h * 64 + wn * 16 + ni * 8 + (lane & 3) * 2;
            *(float2*)(g_ctx + (size_t)tok * D_ + cc) =
                make_float2(acc[mi][ni][0], acc[mi][ni][1]);
            *(float2*)(g_ctx + (size_t)(tok + 8) * D_ + cc) =
                make_float2(acc[mi][ni][2], acc[mi][ni][3]);
        }
}

// ---------------------------------------------------------------------------
extern "C" void kernel_launch(void* const* d_in, const int* in_sizes, int n_in,
                              void* d_out, int out_size)
{
    const float* query = (const float*)d_in[0];
    const float* key_  = (const float*)d_in[1];
    const float* value = (const float*)d_in[2];
    const float* Wq = (const float*)d_in[3];
    const float* bq = (const float*)d_in[4];
    const float* Wk = (const float*)d_in[5];
    const float* bk = (const float*)d_in[6];
    const float* Wv = (const float*)d_in[7];
    const float* bv = (const float*)d_in[8];
    const float* Wo = (const float*)d_in[9];
    const float* bo = (const float*)d_in[10];
    const float* rel_bias = (const float*)d_in[11];
    float* outp = (float*)d_out;

    static float *Qp = nullptr, *Kp = nullptr, *Vp = nullptr, *Cp = nullptr, *Ap = nullptr;
    static __half *Wth = nullptr, *Wtl = nullptr, *Vth = nullptr, *Vtl = nullptr;
    if (!Qp) {
        cudaGetSymbolAddress((void**)&Qp, g_Q);
        cudaGetSymbolAddress((void**)&Kp, g_K);
        cudaGetSymbolAddress((void**)&Vp, g_V);
        cudaGetSymbolAddress((void**)&Cp, g_ctx);
        cudaGetSymbolAddress((void**)&Ap, g_attn);
        cudaGetSymbolAddress((void**)&Wth, g_Wth);
        cudaGetSymbolAddress((void**)&Wtl, g_Wtl);
        cudaGetSymbolAddress((void**)&Vth, g_Vth);
        cudaGetSymbolAddress((void**)&Vtl, g_Vtl);
    }

    float* attn = ((size_t)out_size >= OUT_ELEMS + ATT_ELEMS) ? (outp + OUT_ELEMS) : Ap;
    const size_t WSZ = (size_t)D_ * D_;

    dim3 bT(32, 8);
    dim3 gW(D_ / 32, D_ / 32);
    wsplit<<<gW, bT>>>(Wq, Wth + 0 * WSZ, Wtl + 0 * WSZ);
    wsplit<<<gW, bT>>>(Wk, Wth + 1 * WSZ, Wtl + 1 * WSZ);
    wsplit<<<gW, bT>>>(Wv, Wth + 2 * WSZ, Wtl + 2 * WSZ);
    wsplit<<<gW, bT>>>(Wo, Wth + 3 * WSZ, Wtl + 3 * WSZ);

    dim3 gProj(D_ / 128, BL_ / 128);   // (8, 32)
    proj_tc<<<gProj, 256>>>(query, Wth + 0 * WSZ, Wtl + 0 * WSZ, bq, Qp);
    proj_tc<<<gProj, 256>>>(key_,  Wth + 1 * WSZ, Wtl + 1 * WSZ, bk, Kp);
    proj_tc<<<gProj, 256>>>(value, Wth + 2 * WSZ, Wtl + 2 * WSZ, bv, Vp);

    vsplit<<<dim3(D_ / 32, BL_ / 32), bT>>>(Vp, Vth, Vtl);

    dim3 gScores(L_ / 128, L_ / 128, B_ * H_);  // (16, 16, 32)
    scores_tc<<<gScores, 256>>>(rel_bias, attn);

    softmax_kernel<<<(unsigned)(B_ * H_ * L_), 256>>>(attn);

    dim3 gAV(L_ / 128, B_ * H_);       // (16, 32)
    av_tc<<<gAV, 256>>>(attn);

    proj_tc<<<gProj, 256>>>(Cp, Wth + 3 * WSZ, Wtl + 3 * WSZ, bo, outp);
}

// round 6
// speedup vs baseline: 1.3193x; 1.0083x over previous
#include <cuda_runtime.h>
#include <cuda_fp16.h>
#include <cstdint>
#include <cstddef>

#define B_   2
#define L_   2048
#define D_   1024
#define H_   16
#define HD_  64
#define BL_  (B_ * L_)
#define NBIAS_ 257
#define STR  40   // smem row stride in halfs (80B): conflict-free for ldmatrix

static const size_t OUT_ELEMS = (size_t)BL_ * D_;
static const size_t ATT_ELEMS = (size_t)B_ * H_ * L_ * (size_t)L_;

// Device-global scratch (allocation-free rule)
__device__ float  g_V[(size_t)BL_ * D_];
__device__ __half g_Qh[(size_t)BL_ * D_], g_Ql[(size_t)BL_ * D_];
__device__ __half g_Kh[(size_t)BL_ * D_], g_Kl[(size_t)BL_ * D_];
__device__ __half g_Ch[(size_t)BL_ * D_], g_Cl[(size_t)BL_ * D_];
__device__ __half g_Wth[4ull * D_ * D_];   // transposed weights [n][k], hi
__device__ __half g_Wtl[4ull * D_ * D_];   // lo
__device__ __half g_Vth[(size_t)BL_ * D_]; // V transposed: [(b*16+h)*64+d][tok]
__device__ __half g_Vtl[(size_t)BL_ * D_];
__device__ __half g_Ph[(size_t)B_ * H_ * L_ * (size_t)L_];  // softmax halves
__device__ __half g_Pl[(size_t)B_ * H_ * L_ * (size_t)L_];
__device__ float  g_attn[(size_t)B_ * H_ * L_ * (size_t)L_]; // fallback

// ---------------------------------------------------------------------------
// MMA / ldmatrix helpers
// ---------------------------------------------------------------------------
__device__ __forceinline__ uint32_t smem_u32(const void* p) {
    uint32_t a;
    asm("{ .reg .u64 t; cvta.to.shared.u64 t, %1; cvt.u32.u64 %0, t; }" : "=r"(a) : "l"(p));
    return a;
}
__device__ __forceinline__ void ldsm4(uint32_t r[4], uint32_t addr) {
    asm volatile("ldmatrix.sync.aligned.m8n8.x4.shared.b16 {%0,%1,%2,%3}, [%4];"
                 : "=r"(r[0]), "=r"(r[1]), "=r"(r[2]), "=r"(r[3]) : "r"(addr));
}
__device__ __forceinline__ void ldsm2(uint32_t r[2], uint32_t addr) {
    asm volatile("ldmatrix.sync.aligned.m8n8.x2.shared.b16 {%0,%1}, [%2];"
                 : "=r"(r[0]), "=r"(r[1]) : "r"(addr));
}
__device__ __forceinline__ void mma16816(float c[4], const uint32_t a[4], const uint32_t b[2]) {
    asm volatile("mma.sync.aligned.m16n8k16.row.col.f32.f16.f16.f32 "
                 "{%0,%1,%2,%3}, {%4,%5,%6,%7}, {%8,%9}, {%0,%1,%2,%3};"
                 : "+f"(c[0]), "+f"(c[1]), "+f"(c[2]), "+f"(c[3])
                 : "r"(a[0]), "r"(a[1]), "r"(a[2]), "r"(a[3]), "r"(b[0]), "r"(b[1]));
}

__device__ __forceinline__ uint32_t h2u(__half2 v) { return *reinterpret_cast<uint32_t*>(&v); }

__device__ __forceinline__ void split2(float x, float y, uint32_t& hi, uint32_t& lo) {
    __half h0 = __float2half_rn(x), h1 = __float2half_rn(y);
    __half l0 = __float2half_rn(x - __half2float(h0));
    __half l1 = __float2half_rn(y - __half2float(h1));
    hi = h2u(__halves2half2(h0, h1));
    lo = h2u(__halves2half2(l0, l1));
}

// Load half tile [rows][32] (row stride gs halfs) -> smem (STR stride)
__device__ __forceinline__ void ld_half(const __half* __restrict__ g, int gs,
                                        __half* __restrict__ s, int tid, int rows) {
    int c = tid & 3, r0 = tid >> 2;
    for (int r = r0; r < rows; r += 64) {
        uint4 v = *(const uint4*)(g + (size_t)r * gs + c * 8);
        *(uint4*)(s + r * STR + c * 8) = v;
    }
}

// ---------------------------------------------------------------------------
// Prep kernels
// ---------------------------------------------------------------------------
__global__ void wsplit(const float* __restrict__ W, __half* __restrict__ Th,
                       __half* __restrict__ Tl) {
    __shared__ float t[32][33];
    int bx = blockIdx.x * 32, by = blockIdx.y * 32;
    int tx = threadIdx.x, ty = threadIdx.y;
    for (int i = ty; i < 32; i += 8)
        t[i][tx] = W[(size_t)(by + i) * D_ + bx + tx];
    __syncthreads();
    for (int i = ty; i < 32; i += 8) {
        float v = t[tx][i];   // W[k=by+tx][n=bx+i]
        __half h = __float2half_rn(v);
        Th[(size_t)(bx + i) * D_ + by + tx] = h;
        Tl[(size_t)(bx + i) * D_ + by + tx] = __float2half_rn(v - __half2float(h));
    }
}
__global__ void vsplit(const float* __restrict__ V, __half* __restrict__ Th,
                       __half* __restrict__ Tl) {
    __shared__ float t[32][33];
    int bx = blockIdx.x * 32, by = blockIdx.y * 32;  // bx: feat, by: tok
    int tx = threadIdx.x, ty = threadIdx.y;
    for (int i = ty; i < 32; i += 8)
        t[i][tx] = V[(size_t)(by + i) * D_ + bx + tx];
    __syncthreads();
    int tok = by + tx;
    int b = tok >> 11, tokin = tok & (L_ - 1);
    for (int i = ty; i < 32; i += 8) {
        int f = bx + i;
        float v = t[tx][i];   // V[tok][f]
        size_t row = ((size_t)(b * H_ + (f >> 6))) * 64 + (f & 63);
        __half h = __float2half_rn(v);
        Th[row * L_ + tokin] = h;
        Tl[row * L_ + tokin] = __float2half_rn(v - __half2float(h));
    }
}

// fp32 tile loader w/ split (used only where A is fp32: V-proj input)
__device__ __forceinline__ void ld_splitA(const float* __restrict__ g, int gs,
                                          __half* __restrict__ sh, __half* __restrict__ sl,
                                          int tid, int rows) {
    int c = tid & 7, r0 = tid >> 3;
    for (int r = r0; r < rows; r += 32) {
        float4 v = *(const float4*)(g + (size_t)r * gs + c * 4);
        uint32_t h0, l0, h1, l1;
        split2(v.x, v.y, h0, l0);
        split2(v.z, v.w, h1, l1);
        *(uint2*)(sh + r * STR + c * 4) = make_uint2(h0, h1);
        *(uint2*)(sl + r * STR + c * 4) = make_uint2(l0, l1);
    }
}

// ---------------------------------------------------------------------------
// Projection GEMM: C = A @ W + bias.  M=4096, N=1024, K=1024
// AHALF: A operand pre-split halves (Ah/Al) vs fp32 (A32, split on load)
// EPIHALF: epilogue writes hi/lo halves (Ch/Cl) vs fp32 (C32)
// ---------------------------------------------------------------------------
template <int AHALF, int EPIHALF>
__global__ __launch_bounds__(256) void proj_tc(
    const float* __restrict__ A32,
    const __half* __restrict__ Ahg, const __half* __restrict__ Alg,
    const __half* __restrict__ Bth, const __half* __restrict__ Btl,
    const float* __restrict__ bias,
    float* __restrict__ C32, __half* __restrict__ Ch, __half* __restrict__ Cl)
{
    __shared__ __half sAh[128 * STR], sAl[128 * STR];
    __shared__ __half sBh[128 * STR], sBl[128 * STR];

    const int tid = threadIdx.x, wid = tid >> 5, lane = tid & 31;
    const int wm = wid >> 2, wn = wid & 3;
    const int n0 = blockIdx.x * 128, m0 = blockIdx.y * 128;

    const uint32_t pAh = smem_u32(sAh), pAl = smem_u32(sAl);
    const uint32_t pBh = smem_u32(sBh), pBl = smem_u32(sBl);

    float acc[4][4][4];
#pragma unroll
    for (int i = 0; i < 4; i++)
#pragma unroll
        for (int j = 0; j < 4; j++)
#pragma unroll
            for (int f = 0; f < 4; f++) acc[i][j][f] = 0.0f;

    for (int kt = 0; kt < D_; kt += 32) {
        if (AHALF) {
            ld_half(Ahg + (size_t)m0 * D_ + kt, D_, sAh, tid, 128);
            ld_half(Alg + (size_t)m0 * D_ + kt, D_, sAl, tid, 128);
        } else {
            ld_splitA(A32 + (size_t)m0 * D_ + kt, D_, sAh, sAl, tid, 128);
        }
        ld_half(Bth + (size_t)n0 * D_ + kt, D_, sBh, tid, 128);
        ld_half(Btl + (size_t)n0 * D_ + kt, D_, sBl, tid, 128);
        __syncthreads();
#pragma unroll
        for (int ks = 0; ks < 32; ks += 16) {
            uint32_t ah[4][4], al[4][4], bh[4][2], bl[4][2];
            const uint32_t aoff = (uint32_t)((wm * 64 + (lane & 15)) * STR + ks + (lane >> 4) * 8) * 2;
            const uint32_t boff = (uint32_t)((wn * 32 + (lane & 7)) * STR + ks + ((lane >> 3) & 1) * 8) * 2;
#pragma unroll
            for (int mi = 0; mi < 4; mi++) {
                ldsm4(ah[mi], pAh + aoff + mi * 16 * STR * 2);
                ldsm4(al[mi], pAl + aoff + mi * 16 * STR * 2);
            }
#pragma unroll
            for (int ni = 0; ni < 4; ni++) {
                ldsm2(bh[ni], pBh + boff + ni * 8 * STR * 2);
                ldsm2(bl[ni], pBl + boff + ni * 8 * STR * 2);
            }
#pragma unroll
            for (int mi = 0; mi < 4; mi++)
#pragma unroll
                for (int ni = 0; ni < 4; ni++) {
                    mma16816(acc[mi][ni], ah[mi], bh[ni]);
                    mma16816(acc[mi][ni], ah[mi], bl[ni]);
                    mma16816(acc[mi][ni], al[mi], bh[ni]);
                }
        }
        __syncthreads();
    }

#pragma unroll
    for (int mi = 0; mi < 4; mi++)
#pragma unroll
        for (int ni = 0; ni < 4; ni++) {
            int r = m0 + wm * 64 + mi * 16 + (lane >> 2);
            int cc = n0 + wn * 32 + ni * 8 + (lane & 3) * 2;
            float b0 = bias[cc], b1 = bias[cc + 1];
            float v0 = acc[mi][ni][0] + b0, v1 = acc[mi][ni][1] + b1;
            float v2 = acc[mi][ni][2] + b0, v3 = acc[mi][ni][3] + b1;
            if (EPIHALF) {
                uint32_t h, l;
                split2(v0, v1, h, l);
                *(uint32_t*)(Ch + (size_t)r * D_ + cc) = h;
                *(uint32_t*)(Cl + (size_t)r * D_ + cc) = l;
                split2(v2, v3, h, l);
                *(uint32_t*)(Ch + (size_t)(r + 8) * D_ + cc) = h;
                *(uint32_t*)(Cl + (size_t)(r + 8) * D_ + cc) = l;
            } else {
                *(float2*)(C32 + (size_t)r * D_ + cc) = make_float2(v0, v1);
                *(float2*)(C32 + (size_t)(r + 8) * D_ + cc) = make_float2(v2, v3);
            }
        }
}

// ---------------------------------------------------------------------------
// Scores: S[b,h,q,k] = (Q.K)/8 + rel_bias.  Block 128q x 128k, Kdim=64.
// All operands pre-split halves.
// ---------------------------------------------------------------------------
__global__ __launch_bounds__(256) void scores_tc(
    const float* __restrict__ rel_bias, float* __restrict__ attn)
{
    __shared__ __half sAh[128 * STR], sAl[128 * STR];
    __shared__ __half sBh[128 * STR], sBl[128 * STR];
    __shared__ float sbias[NBIAS_];

    const int tid = threadIdx.x, wid = tid >> 5, lane = tid & 31;
    const int wm = wid >> 2, wn = wid & 3;
    const int bx = blockIdx.x, by = blockIdx.y, bh_ = blockIdx.z;
    const int b = bh_ >> 4, h = bh_ & 15;

    for (int i = tid; i < NBIAS_; i += 256) sbias[i] = rel_bias[i * H_ + h];

    const uint32_t pAh = smem_u32(sAh), pAl = smem_u32(sAl);
    const uint32_t pBh = smem_u32(sBh), pBl = smem_u32(sBl);

    const size_t qb = (size_t)(b * L_ + by * 128) * D_ + h * HD_;
    const size_t kb = (size_t)(b * L_ + bx * 128) * D_ + h * HD_;

    float acc[4][4][4];
#pragma unroll
    for (int i = 0; i < 4; i++)
#pragma unroll
        for (int j = 0; j < 4; j++)
#pragma unroll
            for (int f = 0; f < 4; f++) acc[i][j][f] = 0.0f;

    for (int kt = 0; kt < HD_; kt += 32) {
        ld_half(g_Qh + qb + kt, D_, sAh, tid, 128);
        ld_half(g_Ql + qb + kt, D_, sAl, tid, 128);
        ld_half(g_Kh + kb + kt, D_, sBh, tid, 128);
        ld_half(g_Kl + kb + kt, D_, sBl, tid, 128);
        __syncthreads();
#pragma unroll
        for (int ks = 0; ks < 32; ks += 16) {
            uint32_t ah[4][4], al[4][4], bh[4][2], bl[4][2];
            const uint32_t aoff = (uint32_t)((wm * 64 + (lane & 15)) * STR + ks + (lane >> 4) * 8) * 2;
            const uint32_t boff = (uint32_t)((wn * 32 + (lane & 7)) * STR + ks + ((lane >> 3) & 1) * 8) * 2;
#pragma unroll
            for (int mi = 0; mi < 4; mi++) {
                ldsm4(ah[mi], pAh + aoff + mi * 16 * STR * 2);
                ldsm4(al[mi], pAl + aoff + mi * 16 * STR * 2);
            }
#pragma unroll
            for (int ni = 0; ni < 4; ni++) {
                ldsm2(bh[ni], pBh + boff + ni * 8 * STR * 2);
                ldsm2(bl[ni], pBl + boff + ni * 8 * STR * 2);
            }
#pragma unroll
            for (int mi = 0; mi < 4; mi++)
#pragma unroll
                for (int ni = 0; ni < 4; ni++) {
                    mma16816(acc[mi][ni], ah[mi], bh[ni]);
                    mma16816(acc[mi][ni], ah[mi], bl[ni]);
                    mma16816(acc[mi][ni], al[mi], bh[ni]);
                }
        }
        __syncthreads();
    }

    float* base = attn + (size_t)bh_ * L_ * L_;
#pragma unroll
    for (int mi = 0; mi < 4; mi++)
#pragma unroll
        for (int ni = 0; ni < 4; ni++) {
            int q0 = by * 128 + wm * 64 + mi * 16 + (lane >> 2);
            int kc = bx * 128 + wn * 32 + ni * 8 + (lane & 3) * 2;
#pragma unroll
            for (int half_ = 0; half_ < 2; half_++) {
                int q = q0 + half_ * 8;
                int rel0 = kc - q;     rel0 = rel0 < -128 ? -128 : (rel0 > 128 ? 128 : rel0);
                int rel1 = kc + 1 - q; rel1 = rel1 < -128 ? -128 : (rel1 > 128 ? 128 : rel1);
                float2 o = make_float2(
                    acc[mi][ni][half_ * 2 + 0] * 0.125f + sbias[rel0 + 128],
                    acc[mi][ni][half_ * 2 + 1] * 0.125f + sbias[rel1 + 128]);
                *(float2*)(base + (size_t)q * L_ + kc) = o;
            }
        }
}

// ---------------------------------------------------------------------------
// Row softmax over Lk=2048 in place + emit hi/lo half planes for AV.
// ---------------------------------------------------------------------------
__device__ __forceinline__ float warpMax(float v) {
#pragma unroll
    for (int o = 16; o > 0; o >>= 1) v = fmaxf(v, __shfl_xor_sync(0xffffffffu, v, o));
    return v;
}
__device__ __forceinline__ float warpSum(float v) {
#pragma unroll
    for (int o = 16; o > 0; o >>= 1) v += __shfl_xor_sync(0xffffffffu, v, o);
    return v;
}
__global__ __launch_bounds__(256)
void softmax_kernel(float* __restrict__ attn, __half* __restrict__ Ph,
                    __half* __restrict__ Pl)
{
    __shared__ float sm[8];
    __shared__ float ss[8];
    const size_t row = blockIdx.x;
    float* p = attn + row * (size_t)L_;
    const int tid = threadIdx.x, lane = tid & 31, warp = tid >> 5;

    float4 v0 = ((const float4*)p)[tid];
    float4 v1 = ((const float4*)p)[tid + 256];
    float m = fmaxf(fmaxf(fmaxf(v0.x, v0.y), fmaxf(v0.z, v0.w)),
                    fmaxf(fmaxf(v1.x, v1.y), fmaxf(v1.z, v1.w)));
    m = warpMax(m);
    if (lane == 0) sm[warp] = m;
    __syncthreads();
    if (warp == 0) {
        float t = (lane < 8) ? sm[lane] : -3.4e38f;
        t = warpMax(t);
        if (lane == 0) sm[0] = t;
    }
    __syncthreads();
    m = sm[0];
    v0.x = __expf(v0.x - m); v0.y = __expf(v0.y - m);
    v0.z = __expf(v0.z - m); v0.w = __expf(v0.w - m);
    v1.x = __expf(v1.x - m); v1.y = __expf(v1.y - m);
    v1.z = __expf(v1.z - m); v1.w = __expf(v1.w - m);
    float s = (v0.x + v0.y) + (v0.z + v0.w) + (v1.x + v1.y) + (v1.z + v1.w);
    s = warpSum(s);
    if (lane == 0) ss[warp] = s;
    __syncthreads();
    if (warp == 0) {
        float t = (lane < 8) ? ss[lane] : 0.0f;
        t = warpSum(t);
        if (lane == 0) ss[0] = t;
    }
    __syncthreads();
    float inv = 1.0f / ss[0];
    v0.x *= inv; v0.y *= inv; v0.z *= inv; v0.w *= inv;
    v1.x *= inv; v1.y *= inv; v1.z *= inv; v1.w *= inv;
    ((float4*)p)[tid] = v0;
    ((float4*)p)[tid + 256] = v1;

    // emit half planes
    __half* ph = Ph + row * (size_t)L_;
    __half* pl = Pl + row * (size_t)L_;
    uint32_t h0, l0, h1, l1;
    split2(v0.x, v0.y, h0, l0);
    split2(v0.z, v0.w, h1, l1);
    *(uint2*)(ph + tid * 4) = make_uint2(h0, h1);
    *(uint2*)(pl + tid * 4) = make_uint2(l0, l1);
    split2(v1.x, v1.y, h0, l0);
    split2(v1.z, v1.w, h1, l1);
    *(uint2*)(ph + 1024 + tid * 4) = make_uint2(h0, h1);
    *(uint2*)(pl + 1024 + tid * 4) = make_uint2(l0, l1);
}

// ---------------------------------------------------------------------------
// AV: ctx[tok][h*64+d] = sum_k P[q][k] * Vt[d][k].  Block 128q x 64d, K=2048.
// All operands pre-split halves; epilogue writes ctx halves.
// ---------------------------------------------------------------------------
__global__ __launch_bounds__(256) void av_tc()
{
    __shared__ __half sAh[128 * STR], sAl[128 * STR];
    __shared__ __half sBh[64 * STR], sBl[64 * STR];

    const int tid = threadIdx.x, wid = tid >> 5, lane = tid & 31;
    const int wm = wid >> 2, wn = wid & 3;
    const int by = blockIdx.x, bh_ = blockIdx.y;
    const int b = bh_ >> 4, h = bh_ & 15;

    const uint32_t pAh = smem_u32(sAh), pAl = smem_u32(sAl);
    const uint32_t pBh = smem_u32(sBh), pBl = smem_u32(sBl);

    const size_t pb = ((size_t)bh_ * L_ + by * 128) * L_;
    const size_t vb = (size_t)bh_ * 64 * L_;

    float acc[4][2][4];
#pragma unroll
    for (int i = 0; i < 4; i++)
#pragma unroll
        for (int j = 0; j < 2; j++)
#pragma unroll
            for (int f = 0; f < 4; f++) acc[i][j][f] = 0.0f;

    for (int kt = 0; kt < L_; kt += 32) {
        ld_half(g_Ph + pb + kt, L_, sAh, tid, 128);
        ld_half(g_Pl + pb + kt, L_, sAl, tid, 128);
        ld_half(g_Vth + vb + kt, L_, sBh, tid, 64);
        ld_half(g_Vtl + vb + kt, L_, sBl, tid, 64);
        __syncthreads();
#pragma unroll
        for (int ks = 0; ks < 32; ks += 16) {
            uint32_t ah[4][4], al[4][4], bh[2][2], bl[2][2];
            const uint32_t aoff = (uint32_t)((wm * 64 + (lane & 15)) * STR + ks + (lane >> 4) * 8) * 2;
            const uint32_t boff = (uint32_t)((wn * 16 + (lane & 7)) * STR + ks + ((lane >> 3) & 1) * 8) * 2;
#pragma unroll
            for (int mi = 0; mi < 4; mi++) {
                ldsm4(ah[mi], pAh + aoff + mi * 16 * STR * 2);
                ldsm4(al[mi], pAl + aoff + mi * 16 * STR * 2);
            }
#pragma unroll
            for (int ni = 0; ni < 2; ni++) {
                ldsm2(bh[ni], pBh + boff + ni * 8 * STR * 2);
                ldsm2(bl[ni], pBl + boff + ni * 8 * STR * 2);
            }
#pragma unroll
            for (int mi = 0; mi < 4; mi++)
#pragma unroll
                for (int ni = 0; ni < 2; ni++) {
                    mma16816(acc[mi][ni], ah[mi], bh[ni]);
                    mma16816(acc[mi][ni], ah[mi], bl[ni]);
                    mma16816(acc[mi][ni], al[mi], bh[ni]);
                }
        }
        __syncthreads();
    }

#pragma unroll
    for (int mi = 0; mi < 4; mi++)
#pragma unroll
        for (int ni = 0; ni < 2; ni++) {
            int tok = b * L_ + by * 128 + wm * 64 + mi * 16 + (lane >> 2);
            int cc = h * 64 + wn * 16 + ni * 8 + (lane & 3) * 2;
            uint32_t hh, ll;
            split2(acc[mi][ni][0], acc[mi][ni][1], hh, ll);
            *(uint32_t*)(g_Ch + (size_t)tok * D_ + cc) = hh;
            *(uint32_t*)(g_Cl + (size_t)tok * D_ + cc) = ll;
            split2(acc[mi][ni][2], acc[mi][ni][3], hh, ll);
            *(uint32_t*)(g_Ch + (size_t)(tok + 8) * D_ + cc) = hh;
            *(uint32_t*)(g_Cl + (size_t)(tok + 8) * D_ + cc) = ll;
        }
}

// ---------------------------------------------------------------------------
extern "C" void kernel_launch(void* const* d_in, const int* in_sizes, int n_in,
                              void* d_out, int out_size)
{
    const float* query = (const float*)d_in[0];
    const float* key_  = (const float*)d_in[1];
    const float* value = (const float*)d_in[2];
    const float* Wq = (const float*)d_in[3];
    const float* bq = (const float*)d_in[4];
    const float* Wk = (const float*)d_in[5];
    const float* bk = (const float*)d_in[6];
    const float* Wv = (const float*)d_in[7];
    const float* bv = (const float*)d_in[8];
    const float* Wo = (const float*)d_in[9];
    const float* bo = (const float*)d_in[10];
    const float* rel_bias = (const float*)d_in[11];
    float* outp = (float*)d_out;

    static float *Vp = nullptr, *Ap = nullptr;
    static __half *Wth = nullptr, *Wtl = nullptr, *Vth = nullptr, *Vtl = nullptr;
    static __half *Qh = nullptr, *Ql = nullptr, *Kh = nullptr, *Kl = nullptr;
    static __half *Ch = nullptr, *Cl = nullptr, *Ph = nullptr, *Pl = nullptr;
    if (!Vp) {
        cudaGetSymbolAddress((void**)&Vp, g_V);
        cudaGetSymbolAddress((void**)&Ap, g_attn);
        cudaGetSymbolAddress((void**)&Wth, g_Wth);
        cudaGetSymbolAddress((void**)&Wtl, g_Wtl);
        cudaGetSymbolAddress((void**)&Vth, g_Vth);
        cudaGetSymbolAddress((void**)&Vtl, g_Vtl);
        cudaGetSymbolAddress((void**)&Qh, g_Qh);
        cudaGetSymbolAddress((void**)&Ql, g_Ql);
        cudaGetSymbolAddress((void**)&Kh, g_Kh);
        cudaGetSymbolAddress((void**)&Kl, g_Kl);
        cudaGetSymbolAddress((void**)&Ch, g_Ch);
        cudaGetSymbolAddress((void**)&Cl, g_Cl);
        cudaGetSymbolAddress((void**)&Ph, g_Ph);
        cudaGetSymbolAddress((void**)&Pl, g_Pl);
    }

    float* attn = ((size_t)out_size >= OUT_ELEMS + ATT_ELEMS) ? (outp + OUT_ELEMS) : Ap;
    const size_t WSZ = (size_t)D_ * D_;

    dim3 bT(32, 8);
    dim3 gW(D_ / 32, D_ / 32);
    wsplit<<<gW, bT>>>(Wq, Wth + 0 * WSZ, Wtl + 0 * WSZ);
    wsplit<<<gW, bT>>>(Wk, Wth + 1 * WSZ, Wtl + 1 * WSZ);
    wsplit<<<gW, bT>>>(Wv, Wth + 2 * WSZ, Wtl + 2 * WSZ);
    wsplit<<<gW, bT>>>(Wo, Wth + 3 * WSZ, Wtl + 3 * WSZ);

    dim3 gProj(D_ / 128, BL_ / 128);   // (8, 32)
    // Q, K projections -> half planes
    proj_tc<0, 1><<<gProj, 256>>>(query, nullptr, nullptr, Wth + 0 * WSZ, Wtl + 0 * WSZ,
                                  bq, nullptr, Qh, Ql);
    proj_tc<0, 1><<<gProj, 256>>>(key_, nullptr, nullptr, Wth + 1 * WSZ, Wtl + 1 * WSZ,
                                  bk, nullptr, Kh, Kl);
    // V projection -> fp32 (for transpose+split)
    proj_tc<0, 0><<<gProj, 256>>>(value, nullptr, nullptr, Wth + 2 * WSZ, Wtl + 2 * WSZ,
                                  bv, Vp, nullptr, nullptr);

    vsplit<<<dim3(D_ / 32, BL_ / 32), bT>>>(Vp, Vth, Vtl);

    dim3 gScores(L_ / 128, L_ / 128, B_ * H_);  // (16, 16, 32)
    scores_tc<<<gScores, 256>>>(rel_bias, attn);

    softmax_kernel<<<(unsigned)(B_ * H_ * L_), 256>>>(attn, Ph, Pl);

    dim3 gAV(L_ / 128, B_ * H_);       // (16, 32)
    av_tc<<<gAV, 256>>>();

    // Output projection: ctx halves @ Wo + bo -> fp32 out
    proj_tc<1, 0><<<gProj, 256>>>(nullptr, Ch, Cl, Wth + 3 * WSZ, Wtl + 3 * WSZ,
                                  bo, outp, nullptr, nullptr);
}

// round 7
// speedup vs baseline: 1.8428x; 1.3968x over previous
#include <cuda_runtime.h>
#include <cuda_fp16.h>
#include <cstdint>
#include <cstddef>

#define B_   2
#define L_   2048
#define D_   1024
#define H_   16
#define HD_  64
#define BL_  (B_ * L_)
#define NBIAS_ 257
#define STR  40   // smem row stride (halfs) for 32-wide tiles; ldmatrix conflict-free
#define STR2 72   // smem row stride (halfs) for 64-wide tiles; ldmatrix conflict-free

static const size_t OUT_ELEMS = (size_t)BL_ * D_;
static const size_t ATT_ELEMS = (size_t)B_ * H_ * L_ * (size_t)L_;

// Device-global scratch (allocation-free rule)
__device__ float  g_V[(size_t)BL_ * D_];
__device__ __half g_Qh[(size_t)BL_ * D_], g_Ql[(size_t)BL_ * D_];
__device__ __half g_Kh[(size_t)BL_ * D_], g_Kl[(size_t)BL_ * D_];
__device__ __half g_Ch[(size_t)BL_ * D_], g_Cl[(size_t)BL_ * D_];
__device__ __half g_Wth[4ull * D_ * D_];
__device__ __half g_Wtl[4ull * D_ * D_];
__device__ __half g_Vth[(size_t)BL_ * D_]; // V transposed: [(b*16+h)*64+d][tok]
__device__ __half g_Vtl[(size_t)BL_ * D_];
__device__ __half g_Ph[(size_t)B_ * H_ * L_ * (size_t)L_];
__device__ __half g_Pl[(size_t)B_ * H_ * L_ * (size_t)L_];
__device__ float  g_attn[(size_t)B_ * H_ * L_ * (size_t)L_]; // fallback

// ---------------------------------------------------------------------------
// Helpers
// ---------------------------------------------------------------------------
__device__ __forceinline__ uint32_t smem_u32(const void* p) {
    uint32_t a;
    asm("{ .reg .u64 t; cvta.to.shared.u64 t, %1; cvt.u32.u64 %0, t; }" : "=r"(a) : "l"(p));
    return a;
}
__device__ __forceinline__ void cpa16(uint32_t d, const void* s) {
    asm volatile("cp.async.cg.shared.global [%0], [%1], 16;" :: "r"(d), "l"(s));
}
#define CP_COMMIT() asm volatile("cp.async.commit_group;" ::: "memory")
#define CP_WAIT0()  asm volatile("cp.async.wait_group 0;" ::: "memory")
#define CP_WAIT1()  asm volatile("cp.async.wait_group 1;" ::: "memory")

__device__ __forceinline__ void ldsm4(uint32_t r[4], uint32_t addr) {
    asm volatile("ldmatrix.sync.aligned.m8n8.x4.shared.b16 {%0,%1,%2,%3}, [%4];"
                 : "=r"(r[0]), "=r"(r[1]), "=r"(r[2]), "=r"(r[3]) : "r"(addr));
}
__device__ __forceinline__ void ldsm2(uint32_t r[2], uint32_t addr) {
    asm volatile("ldmatrix.sync.aligned.m8n8.x2.shared.b16 {%0,%1}, [%2];"
                 : "=r"(r[0]), "=r"(r[1]) : "r"(addr));
}
__device__ __forceinline__ void mma16816(float c[4], const uint32_t a[4], const uint32_t b[2]) {
    asm volatile("mma.sync.aligned.m16n8k16.row.col.f32.f16.f16.f32 "
                 "{%0,%1,%2,%3}, {%4,%5,%6,%7}, {%8,%9}, {%0,%1,%2,%3};"
                 : "+f"(c[0]), "+f"(c[1]), "+f"(c[2]), "+f"(c[3])
                 : "r"(a[0]), "r"(a[1]), "r"(a[2]), "r"(a[3]), "r"(b[0]), "r"(b[1]));
}

__device__ __forceinline__ uint32_t h2u(__half2 v) { return *reinterpret_cast<uint32_t*>(&v); }

__device__ __forceinline__ void split2(float x, float y, uint32_t& hi, uint32_t& lo) {
    __half h0 = __float2half_rn(x), h1 = __float2half_rn(y);
    __half l0 = __float2half_rn(x - __half2float(h0));
    __half l1 = __float2half_rn(y - __half2float(h1));
    hi = h2u(__halves2half2(h0, h1));
    lo = h2u(__halves2half2(l0, l1));
}

// Async copy of half tile [rows][32] (gs = global row stride, halfs)
__device__ __forceinline__ void cp_half32(const __half* __restrict__ g, int gs,
                                          uint32_t sm, int tid, int rows) {
    int c = tid & 3, r0 = tid >> 2;
    for (int r = r0; r < rows; r += 64)
        cpa16(sm + (uint32_t)(r * STR + c * 8) * 2, g + (size_t)r * gs + c * 8);
}
// Async copy of half tile [rows][64], stride STR2
__device__ __forceinline__ void cp_half64(const __half* __restrict__ g, int gs,
                                          uint32_t sm, int tid, int rows) {
    int c = tid & 7, r0 = tid >> 3;
    for (int r = r0; r < rows; r += 32)
        cpa16(sm + (uint32_t)(r * STR2 + c * 8) * 2, g + (size_t)r * gs + c * 8);
}
// Synchronous fp32->hi/lo split tile loader [rows][32]
__device__ __forceinline__ void ld_splitA(const float* __restrict__ g, int gs,
                                          __half* __restrict__ sh, __half* __restrict__ sl,
                                          int tid, int rows) {
    int c = tid & 7, r0 = tid >> 3;
    for (int r = r0; r < rows; r += 32) {
        float4 v = *(const float4*)(g + (size_t)r * gs + c * 4);
        uint32_t h0, l0, h1, l1;
        split2(v.x, v.y, h0, l0);
        split2(v.z, v.w, h1, l1);
        *(uint2*)(sh + r * STR + c * 4) = make_uint2(h0, h1);
        *(uint2*)(sl + r * STR + c * 4) = make_uint2(l0, l1);
    }
}

// ---------------------------------------------------------------------------
// Prep kernels
// ---------------------------------------------------------------------------
__global__ void wsplit(const float* __restrict__ W, __half* __restrict__ Th,
                       __half* __restrict__ Tl) {
    __shared__ float t[32][33];
    int bx = blockIdx.x * 32, by = blockIdx.y * 32;
    int tx = threadIdx.x, ty = threadIdx.y;
    for (int i = ty; i < 32; i += 8)
        t[i][tx] = W[(size_t)(by + i) * D_ + bx + tx];
    __syncthreads();
    for (int i = ty; i < 32; i += 8) {
        float v = t[tx][i];
        __half h = __float2half_rn(v);
        Th[(size_t)(bx + i) * D_ + by + tx] = h;
        Tl[(size_t)(bx + i) * D_ + by + tx] = __float2half_rn(v - __half2float(h));
    }
}
__global__ void vsplit(const float* __restrict__ V, __half* __restrict__ Th,
                       __half* __restrict__ Tl) {
    __shared__ float t[32][33];
    int bx = blockIdx.x * 32, by = blockIdx.y * 32;
    int tx = threadIdx.x, ty = threadIdx.y;
    for (int i = ty; i < 32; i += 8)
        t[i][tx] = V[(size_t)(by + i) * D_ + bx + tx];
    __syncthreads();
    int tok = by + tx;
    int b = tok >> 11, tokin = tok & (L_ - 1);
    for (int i = ty; i < 32; i += 8) {
        int f = bx + i;
        float v = t[tx][i];
        size_t row = ((size_t)(b * H_ + (f >> 6))) * 64 + (f & 63);
        __half h = __float2half_rn(v);
        Th[row * L_ + tokin] = h;
        Tl[row * L_ + tokin] = __float2half_rn(v - __half2float(h));
    }
}

// ---------------------------------------------------------------------------
// Projection GEMM, double-buffered cp.async pipeline.
// Dynamic smem: 2 buffers x 4 planes x (128*STR) halfs = 81920 bytes.
// ---------------------------------------------------------------------------
#define PJ_PL   (128 * STR)        // halfs per plane
#define PJ_BUF  (4 * PJ_PL)        // halfs per buffer
#define PJ_SMEM (2 * PJ_BUF * 2)   // bytes

template <int AHALF, int EPIHALF>
__global__ __launch_bounds__(256) void proj_tc(
    const float* __restrict__ A32,
    const __half* __restrict__ Ahg, const __half* __restrict__ Alg,
    const __half* __restrict__ Bth, const __half* __restrict__ Btl,
    const float* __restrict__ bias,
    float* __restrict__ C32, __half* __restrict__ Ch, __half* __restrict__ Cl)
{
    extern __shared__ __half dsm[];
    const int tid = threadIdx.x, wid = tid >> 5, lane = tid & 31;
    const int wm = wid >> 2, wn = wid & 3;
    const int n0 = blockIdx.x * 128, m0 = blockIdx.y * 128;
    const uint32_t sb = smem_u32(dsm);

    float acc[4][4][4];
#pragma unroll
    for (int i = 0; i < 4; i++)
#pragma unroll
        for (int j = 0; j < 4; j++)
#pragma unroll
            for (int f = 0; f < 4; f++) acc[i][j][f] = 0.0f;

    const int NT = D_ / 32;   // 32 k-slices

    // stage(kt, buf): async B planes (+A if AHALF), sync A split if fp32
    auto stage = [&](int kt, int buf) {
        const int k0 = kt * 32;
        __half* base = dsm + buf * PJ_BUF;
        uint32_t ub = sb + (uint32_t)(buf * PJ_BUF) * 2;
        if (AHALF) {
            cp_half32(Ahg + (size_t)m0 * D_ + k0, D_, ub + 0 * PJ_PL * 2, tid, 128);
            cp_half32(Alg + (size_t)m0 * D_ + k0, D_, ub + 1 * PJ_PL * 2, tid, 128);
        }
        cp_half32(Bth + (size_t)n0 * D_ + k0, D_, ub + 2 * PJ_PL * 2, tid, 128);
        cp_half32(Btl + (size_t)n0 * D_ + k0, D_, ub + 3 * PJ_PL * 2, tid, 128);
        CP_COMMIT();
        if (!AHALF)
            ld_splitA(A32 + (size_t)m0 * D_ + k0, D_, base + 0 * PJ_PL, base + 1 * PJ_PL, tid, 128);
    };

    stage(0, 0);
    stage(1, 1);

    for (int kt = 0; kt < NT; kt++) {
        if (kt + 1 < NT) { CP_WAIT1(); } else { CP_WAIT0(); }
        __syncthreads();
        const int buf = kt & 1;
        const uint32_t pAh = sb + (uint32_t)(buf * PJ_BUF + 0 * PJ_PL) * 2;
        const uint32_t pAl = sb + (uint32_t)(buf * PJ_BUF + 1 * PJ_PL) * 2;
        const uint32_t pBh = sb + (uint32_t)(buf * PJ_BUF + 2 * PJ_PL) * 2;
        const uint32_t pBl = sb + (uint32_t)(buf * PJ_BUF + 3 * PJ_PL) * 2;
#pragma unroll
        for (int ks = 0; ks < 32; ks += 16) {
            uint32_t ah[4][4], al[4][4], bh[4][2], bl[4][2];
            const uint32_t aoff = (uint32_t)((wm * 64 + (lane & 15)) * STR + ks + (lane >> 4) * 8) * 2;
            const uint32_t boff = (uint32_t)((wn * 32 + (lane & 7)) * STR + ks + ((lane >> 3) & 1) * 8) * 2;
#pragma unroll
            for (int mi = 0; mi < 4; mi++) {
                ldsm4(ah[mi], pAh + aoff + mi * 16 * STR * 2);
                ldsm4(al[mi], pAl + aoff + mi * 16 * STR * 2);
            }
#pragma unroll
            for (int ni = 0; ni < 4; ni++) {
                ldsm2(bh[ni], pBh + boff + ni * 8 * STR * 2);
                ldsm2(bl[ni], pBl + boff + ni * 8 * STR * 2);
            }
#pragma unroll
            for (int mi = 0; mi < 4; mi++)
#pragma unroll
                for (int ni = 0; ni < 4; ni++) {
                    mma16816(acc[mi][ni], ah[mi], bh[ni]);
                    mma16816(acc[mi][ni], ah[mi], bl[ni]);
                    mma16816(acc[mi][ni], al[mi], bh[ni]);
                }
        }
        __syncthreads();
        if (kt + 2 < NT) stage(kt + 2, buf);
    }

#pragma unroll
    for (int mi = 0; mi < 4; mi++)
#pragma unroll
        for (int ni = 0; ni < 4; ni++) {
            int r = m0 + wm * 64 + mi * 16 + (lane >> 2);
            int cc = n0 + wn * 32 + ni * 8 + (lane & 3) * 2;
            float b0 = bias[cc], b1 = bias[cc + 1];
            float v0 = acc[mi][ni][0] + b0, v1 = acc[mi][ni][1] + b1;
            float v2 = acc[mi][ni][2] + b0, v3 = acc[mi][ni][3] + b1;
            if (EPIHALF) {
                uint32_t h, l;
                split2(v0, v1, h, l);
                *(uint32_t*)(Ch + (size_t)r * D_ + cc) = h;
                *(uint32_t*)(Cl + (size_t)r * D_ + cc) = l;
                split2(v2, v3, h, l);
                *(uint32_t*)(Ch + (size_t)(r + 8) * D_ + cc) = h;
                *(uint32_t*)(Cl + (size_t)(r + 8) * D_ + cc) = l;
            } else {
                *(float2*)(C32 + (size_t)r * D_ + cc) = make_float2(v0, v1);
                *(float2*)(C32 + (size_t)(r + 8) * D_ + cc) = make_float2(v2, v3);
            }
        }
}

// ---------------------------------------------------------------------------
// Scores: whole K=64 resident; one async load, one sync, 4 MMA steps.
// Dynamic smem: 4 planes x (128*STR2) halfs = 73728 bytes.
// ---------------------------------------------------------------------------
#define SC_PL   (128 * STR2)
#define SC_SMEM (4 * SC_PL * 2)

__global__ __launch_bounds__(256) void scores_tc(
    const float* __restrict__ rel_bias, float* __restrict__ attn)
{
    extern __shared__ __half dsm[];
    __shared__ float sbias[NBIAS_];

    const int tid = threadIdx.x, wid = tid >> 5, lane = tid & 31;
    const int wm = wid >> 2, wn = wid & 3;
    const int bx = blockIdx.x, by = blockIdx.y, bh_ = blockIdx.z;
    const int b = bh_ >> 4, h = bh_ & 15;
    const uint32_t sb = smem_u32(dsm);

    const size_t qb = (size_t)(b * L_ + by * 128) * D_ + h * HD_;
    const size_t kb = (size_t)(b * L_ + bx * 128) * D_ + h * HD_;

    cp_half64(g_Qh + qb, D_, sb + 0u * SC_PL * 2, tid, 128);
    cp_half64(g_Ql + qb, D_, sb + 1u * SC_PL * 2, tid, 128);
    cp_half64(g_Kh + kb, D_, sb + 2u * SC_PL * 2, tid, 128);
    cp_half64(g_Kl + kb, D_, sb + 3u * SC_PL * 2, tid, 128);
    CP_COMMIT();

    for (int i = tid; i < NBIAS_; i += 256) sbias[i] = rel_bias[i * H_ + h];

    float acc[4][4][4];
#pragma unroll
    for (int i = 0; i < 4; i++)
#pragma unroll
        for (int j = 0; j < 4; j++)
#pragma unroll
            for (int f = 0; f < 4; f++) acc[i][j][f] = 0.0f;

    CP_WAIT0();
    __syncthreads();

    const uint32_t pAh = sb + 0u * SC_PL * 2, pAl = sb + 1u * SC_PL * 2;
    const uint32_t pBh = sb + 2u * SC_PL * 2, pBl = sb + 3u * SC_PL * 2;
#pragma unroll
    for (int ks = 0; ks < 64; ks += 16) {
        uint32_t ah[4][4], al[4][4], bh[4][2], bl[4][2];
        const uint32_t aoff = (uint32_t)((wm * 64 + (lane & 15)) * STR2 + ks + (lane >> 4) * 8) * 2;
        const uint32_t boff = (uint32_t)((wn * 32 + (lane & 7)) * STR2 + ks + ((lane >> 3) & 1) * 8) * 2;
#pragma unroll
        for (int mi = 0; mi < 4; mi++) {
            ldsm4(ah[mi], pAh + aoff + mi * 16 * STR2 * 2);
            ldsm4(al[mi], pAl + aoff + mi * 16 * STR2 * 2);
        }
#pragma unroll
        for (int ni = 0; ni < 4; ni++) {
            ldsm2(bh[ni], pBh + boff + ni * 8 * STR2 * 2);
            ldsm2(bl[ni], pBl + boff + ni * 8 * STR2 * 2);
        }
#pragma unroll
        for (int mi = 0; mi < 4; mi++)
#pragma unroll
            for (int ni = 0; ni < 4; ni++) {
                mma16816(acc[mi][ni], ah[mi], bh[ni]);
                mma16816(acc[mi][ni], ah[mi], bl[ni]);
                mma16816(acc[mi][ni], al[mi], bh[ni]);
            }
    }

    float* base = attn + (size_t)bh_ * L_ * L_;
#pragma unroll
    for (int mi = 0; mi < 4; mi++)
#pragma unroll
        for (int ni = 0; ni < 4; ni++) {
            int q0 = by * 128 + wm * 64 + mi * 16 + (lane >> 2);
            int kc = bx * 128 + wn * 32 + ni * 8 + (lane & 3) * 2;
#pragma unroll
            for (int half_ = 0; half_ < 2; half_++) {
                int q = q0 + half_ * 8;
                int rel0 = kc - q;     rel0 = rel0 < -128 ? -128 : (rel0 > 128 ? 128 : rel0);
                int rel1 = kc + 1 - q; rel1 = rel1 < -128 ? -128 : (rel1 > 128 ? 128 : rel1);
                float2 o = make_float2(
                    acc[mi][ni][half_ * 2 + 0] * 0.125f + sbias[rel0 + 128],
                    acc[mi][ni][half_ * 2 + 1] * 0.125f + sbias[rel1 + 128]);
                *(float2*)(base + (size_t)q * L_ + kc) = o;
            }
        }
}

// ---------------------------------------------------------------------------
// Row softmax + emit hi/lo half planes.
// ---------------------------------------------------------------------------
__device__ __forceinline__ float warpMax(float v) {
#pragma unroll
    for (int o = 16; o > 0; o >>= 1) v = fmaxf(v, __shfl_xor_sync(0xffffffffu, v, o));
    return v;
}
__device__ __forceinline__ float warpSum(float v) {
#pragma unroll
    for (int o = 16; o > 0; o >>= 1) v += __shfl_xor_sync(0xffffffffu, v, o);
    return v;
}
__global__ __launch_bounds__(256)
void softmax_kernel(float* __restrict__ attn, __half* __restrict__ Ph,
                    __half* __restrict__ Pl)
{
    __shared__ float sm[8];
    __shared__ float ss[8];
    const size_t row = blockIdx.x;
    float* p = attn + row * (size_t)L_;
    const int tid = threadIdx.x, lane = tid & 31, warp = tid >> 5;

    float4 v0 = ((const float4*)p)[tid];
    float4 v1 = ((const float4*)p)[tid + 256];
    float m = fmaxf(fmaxf(fmaxf(v0.x, v0.y), fmaxf(v0.z, v0.w)),
                    fmaxf(fmaxf(v1.x, v1.y), fmaxf(v1.z, v1.w)));
    m = warpMax(m);
    if (lane == 0) sm[warp] = m;
    __syncthreads();
    if (warp == 0) {
        float t = (lane < 8) ? sm[lane] : -3.4e38f;
        t = warpMax(t);
        if (lane == 0) sm[0] = t;
    }
    __syncthreads();
    m = sm[0];
    v0.x = __expf(v0.x - m); v0.y = __expf(v0.y - m);
    v0.z = __expf(v0.z - m); v0.w = __expf(v0.w - m);
    v1.x = __expf(v1.x - m); v1.y = __expf(v1.y - m);
    v1.z = __expf(v1.z - m); v1.w = __expf(v1.w - m);
    float s = (v0.x + v0.y) + (v0.z + v0.w) + (v1.x + v1.y) + (v1.z + v1.w);
    s = warpSum(s);
    if (lane == 0) ss[warp] = s;
    __syncthreads();
    if (warp == 0) {
        float t = (lane < 8) ? ss[lane] : 0.0f;
        t = warpSum(t);
        if (lane == 0) ss[0] = t;
    }
    __syncthreads();
    float inv = 1.0f / ss[0];
    v0.x *= inv; v0.y *= inv; v0.z *= inv; v0.w *= inv;
    v1.x *= inv; v1.y *= inv; v1.z *= inv; v1.w *= inv;
    ((float4*)p)[tid] = v0;
    ((float4*)p)[tid + 256] = v1;

    __half* ph = Ph + row * (size_t)L_;
    __half* pl = Pl + row * (size_t)L_;
    uint32_t h0, l0, h1, l1;
    split2(v0.x, v0.y, h0, l0);
    split2(v0.z, v0.w, h1, l1);
    *(uint2*)(ph + tid * 4) = make_uint2(h0, h1);
    *(uint2*)(pl + tid * 4) = make_uint2(l0, l1);
    split2(v1.x, v1.y, h0, l0);
    split2(v1.z, v1.w, h1, l1);
    *(uint2*)(ph + 1024 + tid * 4) = make_uint2(h0, h1);
    *(uint2*)(pl + 1024 + tid * 4) = make_uint2(l0, l1);
}

// ---------------------------------------------------------------------------
// AV: double-buffered cp.async pipeline. Block 128q x 64d, K=2048.
// Dynamic smem: 2 x (2*128*STR + 2*64*STR) halfs = 61440 bytes.
// ---------------------------------------------------------------------------
#define AV_APL  (128 * STR)
#define AV_BPL  (64 * STR)
#define AV_BUF  (2 * AV_APL + 2 * AV_BPL)
#define AV_SMEM (2 * AV_BUF * 2)

__global__ __launch_bounds__(256) void av_tc()
{
    extern __shared__ __half dsm[];
    const int tid = threadIdx.x, wid = tid >> 5, lane = tid & 31;
    const int wm = wid >> 2, wn = wid & 3;
    const int by = blockIdx.x, bh_ = blockIdx.y;
    const int b = bh_ >> 4, h = bh_ & 15;
    const uint32_t sb = smem_u32(dsm);

    const size_t pb = ((size_t)bh_ * L_ + by * 128) * L_;
    const size_t vb = (size_t)bh_ * 64 * L_;

    float acc[4][2][4];
#pragma unroll
    for (int i = 0; i < 4; i++)
#pragma unroll
        for (int j = 0; j < 2; j++)
#pragma unroll
            for (int f = 0; f < 4; f++) acc[i][j][f] = 0.0f;

    const int NT = L_ / 32;   // 64 slices

    auto stage = [&](int kt, int buf) {
        const int k0 = kt * 32;
        uint32_t ub = sb + (uint32_t)(buf * AV_BUF) * 2;
        cp_half32(g_Ph + pb + k0, L_, ub, tid, 128);
        cp_half32(g_Pl + pb + k0, L_, ub + (uint32_t)AV_APL * 2, tid, 128);
        cp_half32(g_Vth + vb + k0, L_, ub + (uint32_t)(2 * AV_APL) * 2, tid, 64);
        cp_half32(g_Vtl + vb + k0, L_, ub + (uint32_t)(2 * AV_APL + AV_BPL) * 2, tid, 64);
        CP_COMMIT();
    };

    stage(0, 0);
    stage(1, 1);

    for (int kt = 0; kt < NT; kt++) {
        if (kt + 1 < NT) { CP_WAIT1(); } else { CP_WAIT0(); }
        __syncthreads();
        const int buf = kt & 1;
        const uint32_t pAh = sb + (uint32_t)(buf * AV_BUF) * 2;
        const uint32_t pAl = pAh + (uint32_t)AV_APL * 2;
        const uint32_t pBh = pAh + (uint32_t)(2 * AV_APL) * 2;
        const uint32_t pBl = pAh + (uint32_t)(2 * AV_APL + AV_BPL) * 2;
#pragma unroll
        for (int ks = 0; ks < 32; ks += 16) {
            uint32_t ah[4][4], al[4][4], bh[2][2], bl[2][2];
            const uint32_t aoff = (uint32_t)((wm * 64 + (lane & 15)) * STR + ks + (lane >> 4) * 8) * 2;
            const uint32_t boff = (uint32_t)((wn * 16 + (lane & 7)) * STR + ks + ((lane >> 3) & 1) * 8) * 2;
#pragma unroll
            for (int mi = 0; mi < 4; mi++) {
                ldsm4(ah[mi], pAh + aoff + mi * 16 * STR * 2);
                ldsm4(al[mi], pAl + aoff + mi * 16 * STR * 2);
            }
#pragma unroll
            for (int ni = 0; ni < 2; ni++) {
                ldsm2(bh[ni], pBh + boff + ni * 8 * STR * 2);
                ldsm2(bl[ni], pBl + boff + ni * 8 * STR * 2);
            }
#pragma unroll
            for (int mi = 0; mi < 4; mi++)
#pragma unroll
                for (int ni = 0; ni < 2; ni++) {
                    mma16816(acc[mi][ni], ah[mi], bh[ni]);
                    mma16816(acc[mi][ni], ah[mi], bl[ni]);
                    mma16816(acc[mi][ni], al[mi], bh[ni]);
                }
        }
        __syncthreads();
        if (kt + 2 < NT) stage(kt + 2, buf);
    }

#pragma unroll
    for (int mi = 0; mi < 4; mi++)
#pragma unroll
        for (int ni = 0; ni < 2; ni++) {
            int tok = b * L_ + by * 128 + wm * 64 + mi * 16 + (lane >> 2);
            int cc = h * 64 + wn * 16 + ni * 8 + (lane & 3) * 2;
            uint32_t hh, ll;
            split2(acc[mi][ni][0], acc[mi][ni][1], hh, ll);
            *(uint32_t*)(g_Ch + (size_t)tok * D_ + cc) = hh;
            *(uint32_t*)(g_Cl + (size_t)tok * D_ + cc) = ll;
            split2(acc[mi][ni][2], acc[mi][ni][3], hh, ll);
            *(uint32_t*)(g_Ch + (size_t)(tok + 8) * D_ + cc) = hh;
            *(uint32_t*)(g_Cl + (size_t)(tok + 8) * D_ + cc) = ll;
        }
}

// ---------------------------------------------------------------------------
extern "C" void kernel_launch(void* const* d_in, const int* in_sizes, int n_in,
                              void* d_out, int out_size)
{
    const float* query = (const float*)d_in[0];
    const float* key_  = (const float*)d_in[1];
    const float* value = (const float*)d_in[2];
    const float* Wq = (const float*)d_in[3];
    const float* bq = (const float*)d_in[4];
    const float* Wk = (const float*)d_in[5];
    const float* bk = (const float*)d_in[6];
    const float* Wv = (const float*)d_in[7];
    const float* bv = (const float*)d_in[8];
    const float* Wo = (const float*)d_in[9];
    const float* bo = (const float*)d_in[10];
    const float* rel_bias = (const float*)d_in[11];
    float* outp = (float*)d_out;

    static float *Vp = nullptr, *Ap = nullptr;
    static __half *Wth = nullptr, *Wtl = nullptr, *Vth = nullptr, *Vtl = nullptr;
    static __half *Qh = nullptr, *Ql = nullptr, *Kh = nullptr, *Kl = nullptr;
    static __half *Ch = nullptr, *Cl = nullptr, *Ph = nullptr, *Pl = nullptr;
    if (!Vp) {
        cudaGetSymbolAddress((void**)&Vp, g_V);
        cudaGetSymbolAddress((void**)&Ap, g_attn);
        cudaGetSymbolAddress((void**)&Wth, g_Wth);
        cudaGetSymbolAddress((void**)&Wtl, g_Wtl);
        cudaGetSymbolAddress((void**)&Vth, g_Vth);
        cudaGetSymbolAddress((void**)&Vtl, g_Vtl);
        cudaGetSymbolAddress((void**)&Qh, g_Qh);
        cudaGetSymbolAddress((void**)&Ql, g_Ql);
        cudaGetSymbolAddress((void**)&Kh, g_Kh);
        cudaGetSymbolAddress((void**)&Kl, g_Kl);
        cudaGetSymbolAddress((void**)&Ch, g_Ch);
        cudaGetSymbolAddress((void**)&Cl, g_Cl);
        cudaGetSymbolAddress((void**)&Ph, g_Ph);
        cudaGetSymbolAddress((void**)&Pl, g_Pl);
        cudaFuncSetAttribute(proj_tc<0, 0>, cudaFuncAttributeMaxDynamicSharedMemorySize, PJ_SMEM);
        cudaFuncSetAttribute(proj_tc<0, 1>, cudaFuncAttributeMaxDynamicSharedMemorySize, PJ_SMEM);
        cudaFuncSetAttribute(proj_tc<1, 0>, cudaFuncAttributeMaxDynamicSharedMemorySize, PJ_SMEM);
        cudaFuncSetAttribute(scores_tc, cudaFuncAttributeMaxDynamicSharedMemorySize, SC_SMEM);
        cudaFuncSetAttribute(av_tc, cudaFuncAttributeMaxDynamicSharedMemorySize, AV_SMEM);
    }

    float* attn = ((size_t)out_size >= OUT_ELEMS + ATT_ELEMS) ? (outp + OUT_ELEMS) : Ap;
    const size_t WSZ = (size_t)D_ * D_;

    dim3 bT(32, 8);
    dim3 gW(D_ / 32, D_ / 32);
    wsplit<<<gW, bT>>>(Wq, Wth + 0 * WSZ, Wtl + 0 * WSZ);
    wsplit<<<gW, bT>>>(Wk, Wth + 1 * WSZ, Wtl + 1 * WSZ);
    wsplit<<<gW, bT>>>(Wv, Wth + 2 * WSZ, Wtl + 2 * WSZ);
    wsplit<<<gW, bT>>>(Wo, Wth + 3 * WSZ, Wtl + 3 * WSZ);

    dim3 gProj(D_ / 128, BL_ / 128);   // (8, 32)
    proj_tc<0, 1><<<gProj, 256, PJ_SMEM>>>(query, nullptr, nullptr, Wth + 0 * WSZ, Wtl + 0 * WSZ,
                                           bq, nullptr, Qh, Ql);
    proj_tc<0, 1><<<gProj, 256, PJ_SMEM>>>(key_, nullptr, nullptr, Wth + 1 * WSZ, Wtl + 1 * WSZ,
                                           bk, nullptr, Kh, Kl);
    proj_tc<0, 0><<<gProj, 256, PJ_SMEM>>>(value, nullptr, nullptr, Wth + 2 * WSZ, Wtl + 2 * WSZ,
                                           bv, Vp, nullptr, nullptr);

    vsplit<<<dim3(D_ / 32, BL_ / 32), bT>>>(Vp, Vth, Vtl);

    dim3 gScores(L_ / 128, L_ / 128, B_ * H_);  // (16, 16, 32)
    scores_tc<<<gScores, 256, SC_SMEM>>>(rel_bias, attn);

    softmax_kernel<<<(unsigned)(B_ * H_ * L_), 256>>>(attn, Ph, Pl);

    dim3 gAV(L_ / 128, B_ * H_);       // (16, 32)
    av_tc<<<gAV, 256, AV_SMEM>>>();

    proj_tc<1, 0><<<gProj, 256, PJ_SMEM>>>(nullptr, Ch, Cl, Wth + 3 * WSZ, Wtl + 3 * WSZ,
                                           bo, outp, nullptr, nullptr);
}

// round 8
// speedup vs baseline: 1.9427x; 1.0542x over previous
#include <cuda_runtime.h>
#include <cuda_fp16.h>
#include <cstdint>
#include <cstddef>

#define B_   2
#define L_   2048
#define D_   1024
#define H_   16
#define HD_  64
#define BL_  (B_ * L_)
#define NBIAS_ 257
#define STR  40   // smem row stride (halfs) for 32-wide half tiles
#define STR2 72   // smem row stride (halfs) for 64-wide half tiles
#define SRF  36   // smem row stride (floats) for 32-wide fp32 tiles

static const size_t OUT_ELEMS = (size_t)BL_ * D_;
static const size_t ATT_ELEMS = (size_t)B_ * H_ * L_ * (size_t)L_;

// Device-global scratch (allocation-free rule)
__device__ float  g_V[(size_t)BL_ * D_];
__device__ __half g_Qh[(size_t)BL_ * D_], g_Ql[(size_t)BL_ * D_];
__device__ __half g_Kh[(size_t)BL_ * D_], g_Kl[(size_t)BL_ * D_];
__device__ __half g_Ch[(size_t)BL_ * D_], g_Cl[(size_t)BL_ * D_];
__device__ __half g_Wth[4ull * D_ * D_];
__device__ __half g_Wtl[4ull * D_ * D_];
__device__ __half g_Vth[(size_t)BL_ * D_]; // V transposed: [(b*16+h)*64+d][tok]
__device__ __half g_Vtl[(size_t)BL_ * D_];
__device__ float2 g_stats[(size_t)B_ * H_ * L_];   // per-row (max, 1/sum)
__device__ float  g_attn[(size_t)B_ * H_ * L_ * (size_t)L_]; // fallback

// ---------------------------------------------------------------------------
// Helpers
// ---------------------------------------------------------------------------
__device__ __forceinline__ uint32_t smem_u32(const void* p) {
    uint32_t a;
    asm("{ .reg .u64 t; cvta.to.shared.u64 t, %1; cvt.u32.u64 %0, t; }" : "=r"(a) : "l"(p));
    return a;
}
__device__ __forceinline__ void cpa16(uint32_t d, const void* s) {
    asm volatile("cp.async.cg.shared.global [%0], [%1], 16;" :: "r"(d), "l"(s));
}
#define CP_COMMIT() asm volatile("cp.async.commit_group;" ::: "memory")
#define CP_WAIT0()  asm volatile("cp.async.wait_group 0;" ::: "memory")
#define CP_WAIT1()  asm volatile("cp.async.wait_group 1;" ::: "memory")

__device__ __forceinline__ void ldsm4(uint32_t r[4], uint32_t addr) {
    asm volatile("ldmatrix.sync.aligned.m8n8.x4.shared.b16 {%0,%1,%2,%3}, [%4];"
                 : "=r"(r[0]), "=r"(r[1]), "=r"(r[2]), "=r"(r[3]) : "r"(addr));
}
__device__ __forceinline__ void ldsm2(uint32_t r[2], uint32_t addr) {
    asm volatile("ldmatrix.sync.aligned.m8n8.x2.shared.b16 {%0,%1}, [%2];"
                 : "=r"(r[0]), "=r"(r[1]) : "r"(addr));
}
__device__ __forceinline__ void mma16816(float c[4], const uint32_t a[4], const uint32_t b[2]) {
    asm volatile("mma.sync.aligned.m16n8k16.row.col.f32.f16.f16.f32 "
                 "{%0,%1,%2,%3}, {%4,%5,%6,%7}, {%8,%9}, {%0,%1,%2,%3};"
                 : "+f"(c[0]), "+f"(c[1]), "+f"(c[2]), "+f"(c[3])
                 : "r"(a[0]), "r"(a[1]), "r"(a[2]), "r"(a[3]), "r"(b[0]), "r"(b[1]));
}

__device__ __forceinline__ uint32_t h2u(__half2 v) { return *reinterpret_cast<uint32_t*>(&v); }

__device__ __forceinline__ void split2(float x, float y, uint32_t& hi, uint32_t& lo) {
    __half h0 = __float2half_rn(x), h1 = __float2half_rn(y);
    __half l0 = __float2half_rn(x - __half2float(h0));
    __half l1 = __float2half_rn(y - __half2float(h1));
    hi = h2u(__halves2half2(h0, h1));
    lo = h2u(__halves2half2(l0, l1));
}

// Async copy of half tile [rows][32] (gs = global row stride, halfs)
__device__ __forceinline__ void cp_half32(const __half* __restrict__ g, int gs,
                                          uint32_t sm, int tid, int rows) {
    int c = tid & 3, r0 = tid >> 2;
    for (int r = r0; r < rows; r += 64)
        cpa16(sm + (uint32_t)(r * STR + c * 8) * 2, g + (size_t)r * gs + c * 8);
}
// Async copy of half tile [rows][64], stride STR2
__device__ __forceinline__ void cp_half64(const __half* __restrict__ g, int gs,
                                          uint32_t sm, int tid, int rows) {
    int c = tid & 7, r0 = tid >> 3;
    for (int r = r0; r < rows; r += 32)
        cpa16(sm + (uint32_t)(r * STR2 + c * 8) * 2, g + (size_t)r * gs + c * 8);
}
// Synchronous fp32->hi/lo split tile loader [rows][32]
__device__ __forceinline__ void ld_splitA(const float* __restrict__ g, int gs,
                                          __half* __restrict__ sh, __half* __restrict__ sl,
                                          int tid, int rows) {
    int c = tid & 7, r0 = tid >> 3;
    for (int r = r0; r < rows; r += 32) {
        float4 v = *(const float4*)(g + (size_t)r * gs + c * 4);
        uint32_t h0, l0, h1, l1;
        split2(v.x, v.y, h0, l0);
        split2(v.z, v.w, h1, l1);
        *(uint2*)(sh + r * STR + c * 4) = make_uint2(h0, h1);
        *(uint2*)(sl + r * STR + c * 4) = make_uint2(l0, l1);
    }
}

// ---------------------------------------------------------------------------
// Prep kernels
// ---------------------------------------------------------------------------
__global__ void wsplit4(const float* __restrict__ W0, const float* __restrict__ W1,
                        const float* __restrict__ W2, const float* __restrict__ W3,
                        __half* __restrict__ Th, __half* __restrict__ Tl) {
    __shared__ float t[32][33];
    const float* Ws[4] = {W0, W1, W2, W3};
    const float* W = Ws[blockIdx.z];
    __half* th = Th + (size_t)blockIdx.z * D_ * D_;
    __half* tl = Tl + (size_t)blockIdx.z * D_ * D_;
    int bx = blockIdx.x * 32, by = blockIdx.y * 32;
    int tx = threadIdx.x, ty = threadIdx.y;
    for (int i = ty; i < 32; i += 8)
        t[i][tx] = W[(size_t)(by + i) * D_ + bx + tx];
    __syncthreads();
    for (int i = ty; i < 32; i += 8) {
        float v = t[tx][i];
        __half h = __float2half_rn(v);
        th[(size_t)(bx + i) * D_ + by + tx] = h;
        tl[(size_t)(bx + i) * D_ + by + tx] = __float2half_rn(v - __half2float(h));
    }
}
__global__ void vsplit(const float* __restrict__ V, __half* __restrict__ Th,
                       __half* __restrict__ Tl) {
    __shared__ float t[32][33];
    int bx = blockIdx.x * 32, by = blockIdx.y * 32;
    int tx = threadIdx.x, ty = threadIdx.y;
    for (int i = ty; i < 32; i += 8)
        t[i][tx] = V[(size_t)(by + i) * D_ + bx + tx];
    __syncthreads();
    int tok = by + tx;
    int b = tok >> 11, tokin = tok & (L_ - 1);
    for (int i = ty; i < 32; i += 8) {
        int f = bx + i;
        float v = t[tx][i];
        size_t row = ((size_t)(b * H_ + (f >> 6))) * 64 + (f & 63);
        __half h = __float2half_rn(v);
        Th[row * L_ + tokin] = h;
        Tl[row * L_ + tokin] = __float2half_rn(v - __half2float(h));
    }
}

// ---------------------------------------------------------------------------
// Projection GEMM, double-buffered cp.async pipeline.
// ---------------------------------------------------------------------------
#define PJ_PL   (128 * STR)
#define PJ_BUF  (4 * PJ_PL)
#define PJ_SMEM (2 * PJ_BUF * 2)

template <int AHALF, int EPIHALF>
__global__ __launch_bounds__(256) void proj_tc(
    const float* __restrict__ A32,
    const __half* __restrict__ Ahg, const __half* __restrict__ Alg,
    const __half* __restrict__ Bth, const __half* __restrict__ Btl,
    const float* __restrict__ bias,
    float* __restrict__ C32, __half* __restrict__ Ch, __half* __restrict__ Cl)
{
    extern __shared__ __half dsm[];
    const int tid = threadIdx.x, wid = tid >> 5, lane = tid & 31;
    const int wm = wid >> 2, wn = wid & 3;
    const int n0 = blockIdx.x * 128, m0 = blockIdx.y * 128;
    const uint32_t sb = smem_u32(dsm);

    float acc[4][4][4];
#pragma unroll
    for (int i = 0; i < 4; i++)
#pragma unroll
        for (int j = 0; j < 4; j++)
#pragma unroll
            for (int f = 0; f < 4; f++) acc[i][j][f] = 0.0f;

    const int NT = D_ / 32;

    auto stage = [&](int kt, int buf) {
        const int k0 = kt * 32;
        __half* base = dsm + buf * PJ_BUF;
        uint32_t ub = sb + (uint32_t)(buf * PJ_BUF) * 2;
        if (AHALF) {
            cp_half32(Ahg + (size_t)m0 * D_ + k0, D_, ub + 0 * PJ_PL * 2, tid, 128);
            cp_half32(Alg + (size_t)m0 * D_ + k0, D_, ub + 1 * PJ_PL * 2, tid, 128);
        }
        cp_half32(Bth + (size_t)n0 * D_ + k0, D_, ub + 2 * PJ_PL * 2, tid, 128);
        cp_half32(Btl + (size_t)n0 * D_ + k0, D_, ub + 3 * PJ_PL * 2, tid, 128);
        CP_COMMIT();
        if (!AHALF)
            ld_splitA(A32 + (size_t)m0 * D_ + k0, D_, base + 0 * PJ_PL, base + 1 * PJ_PL, tid, 128);
    };

    stage(0, 0);
    stage(1, 1);

    for (int kt = 0; kt < NT; kt++) {
        if (kt + 1 < NT) { CP_WAIT1(); } else { CP_WAIT0(); }
        __syncthreads();
        const int buf = kt & 1;
        const uint32_t pAh = sb + (uint32_t)(buf * PJ_BUF + 0 * PJ_PL) * 2;
        const uint32_t pAl = sb + (uint32_t)(buf * PJ_BUF + 1 * PJ_PL) * 2;
        const uint32_t pBh = sb + (uint32_t)(buf * PJ_BUF + 2 * PJ_PL) * 2;
        const uint32_t pBl = sb + (uint32_t)(buf * PJ_BUF + 3 * PJ_PL) * 2;
#pragma unroll
        for (int ks = 0; ks < 32; ks += 16) {
            uint32_t ah[4][4], al[4][4], bh[4][2], bl[4][2];
            const uint32_t aoff = (uint32_t)((wm * 64 + (lane & 15)) * STR + ks + (lane >> 4) * 8) * 2;
            const uint32_t boff = (uint32_t)((wn * 32 + (lane & 7)) * STR + ks + ((lane >> 3) & 1) * 8) * 2;
#pragma unroll
            for (int mi = 0; mi < 4; mi++) {
                ldsm4(ah[mi], pAh + aoff + mi * 16 * STR * 2);
                ldsm4(al[mi], pAl + aoff + mi * 16 * STR * 2);
            }
#pragma unroll
            for (int ni = 0; ni < 4; ni++) {
                ldsm2(bh[ni], pBh + boff + ni * 8 * STR * 2);
                ldsm2(bl[ni], pBl + boff + ni * 8 * STR * 2);
            }
#pragma unroll
            for (int mi = 0; mi < 4; mi++)
#pragma unroll
                for (int ni = 0; ni < 4; ni++) {
                    mma16816(acc[mi][ni], ah[mi], bh[ni]);
                    mma16816(acc[mi][ni], ah[mi], bl[ni]);
                    mma16816(acc[mi][ni], al[mi], bh[ni]);
                }
        }
        __syncthreads();
        if (kt + 2 < NT) stage(kt + 2, buf);
    }

#pragma unroll
    for (int mi = 0; mi < 4; mi++)
#pragma unroll
        for (int ni = 0; ni < 4; ni++) {
            int r = m0 + wm * 64 + mi * 16 + (lane >> 2);
            int cc = n0 + wn * 32 + ni * 8 + (lane & 3) * 2;
            float b0 = bias[cc], b1 = bias[cc + 1];
            float v0 = acc[mi][ni][0] + b0, v1 = acc[mi][ni][1] + b1;
            float v2 = acc[mi][ni][2] + b0, v3 = acc[mi][ni][3] + b1;
            if (EPIHALF) {
                uint32_t h, l;
                split2(v0, v1, h, l);
                *(uint32_t*)(Ch + (size_t)r * D_ + cc) = h;
                *(uint32_t*)(Cl + (size_t)r * D_ + cc) = l;
                split2(v2, v3, h, l);
                *(uint32_t*)(Ch + (size_t)(r + 8) * D_ + cc) = h;
                *(uint32_t*)(Cl + (size_t)(r + 8) * D_ + cc) = l;
            } else {
                *(float2*)(C32 + (size_t)r * D_ + cc) = make_float2(v0, v1);
                *(float2*)(C32 + (size_t)(r + 8) * D_ + cc) = make_float2(v2, v3);
            }
        }
}

// ---------------------------------------------------------------------------
// Scores: whole K=64 resident.
// ---------------------------------------------------------------------------
#define SC_PL   (128 * STR2)
#define SC_SMEM (4 * SC_PL * 2)

__global__ __launch_bounds__(256) void scores_tc(
    const float* __restrict__ rel_bias, float* __restrict__ attn)
{
    extern __shared__ __half dsm[];
    __shared__ float sbias[NBIAS_];

    const int tid = threadIdx.x, wid = tid >> 5, lane = tid & 31;
    const int wm = wid >> 2, wn = wid & 3;
    const int bx = blockIdx.x, by = blockIdx.y, bh_ = blockIdx.z;
    const int b = bh_ >> 4, h = bh_ & 15;
    const uint32_t sb = smem_u32(dsm);

    const size_t qb = (size_t)(b * L_ + by * 128) * D_ + h * HD_;
    const size_t kb = (size_t)(b * L_ + bx * 128) * D_ + h * HD_;

    cp_half64(g_Qh + qb, D_, sb + 0u * SC_PL * 2, tid, 128);
    cp_half64(g_Ql + qb, D_, sb + 1u * SC_PL * 2, tid, 128);
    cp_half64(g_Kh + kb, D_, sb + 2u * SC_PL * 2, tid, 128);
    cp_half64(g_Kl + kb, D_, sb + 3u * SC_PL * 2, tid, 128);
    CP_COMMIT();

    for (int i = tid; i < NBIAS_; i += 256) sbias[i] = rel_bias[i * H_ + h];

    float acc[4][4][4];
#pragma unroll
    for (int i = 0; i < 4; i++)
#pragma unroll
        for (int j = 0; j < 4; j++)
#pragma unroll
            for (int f = 0; f < 4; f++) acc[i][j][f] = 0.0f;

    CP_WAIT0();
    __syncthreads();

    const uint32_t pAh = sb + 0u * SC_PL * 2, pAl = sb + 1u * SC_PL * 2;
    const uint32_t pBh = sb + 2u * SC_PL * 2, pBl = sb + 3u * SC_PL * 2;
#pragma unroll
    for (int ks = 0; ks < 64; ks += 16) {
        uint32_t ah[4][4], al[4][4], bh[4][2], bl[4][2];
        const uint32_t aoff = (uint32_t)((wm * 64 + (lane & 15)) * STR2 + ks + (lane >> 4) * 8) * 2;
        const uint32_t boff = (uint32_t)((wn * 32 + (lane & 7)) * STR2 + ks + ((lane >> 3) & 1) * 8) * 2;
#pragma unroll
        for (int mi = 0; mi < 4; mi++) {
            ldsm4(ah[mi], pAh + aoff + mi * 16 * STR2 * 2);
            ldsm4(al[mi], pAl + aoff + mi * 16 * STR2 * 2);
        }
#pragma unroll
        for (int ni = 0; ni < 4; ni++) {
            ldsm2(bh[ni], pBh + boff + ni * 8 * STR2 * 2);
            ldsm2(bl[ni], pBl + boff + ni * 8 * STR2 * 2);
        }
#pragma unroll
        for (int mi = 0; mi < 4; mi++)
#pragma unroll
            for (int ni = 0; ni < 4; ni++) {
                mma16816(acc[mi][ni], ah[mi], bh[ni]);
                mma16816(acc[mi][ni], ah[mi], bl[ni]);
                mma16816(acc[mi][ni], al[mi], bh[ni]);
            }
    }

    float* base = attn + (size_t)bh_ * L_ * L_;
#pragma unroll
    for (int mi = 0; mi < 4; mi++)
#pragma unroll
        for (int ni = 0; ni < 4; ni++) {
            int q0 = by * 128 + wm * 64 + mi * 16 + (lane >> 2);
            int kc = bx * 128 + wn * 32 + ni * 8 + (lane & 3) * 2;
#pragma unroll
            for (int half_ = 0; half_ < 2; half_++) {
                int q = q0 + half_ * 8;
                int rel0 = kc - q;     rel0 = rel0 < -128 ? -128 : (rel0 > 128 ? 128 : rel0);
                int rel1 = kc + 1 - q; rel1 = rel1 < -128 ? -128 : (rel1 > 128 ? 128 : rel1);
                float2 o = make_float2(
                    acc[mi][ni][half_ * 2 + 0] * 0.125f + sbias[rel0 + 128],
                    acc[mi][ni][half_ * 2 + 1] * 0.125f + sbias[rel1 + 128]);
                *(float2*)(base + (size_t)q * L_ + kc) = o;
            }
        }
}

// ---------------------------------------------------------------------------
// Row stats: per row of S, compute (max, 1/sum(exp(S-max))). Warp per row.
// ---------------------------------------------------------------------------
__device__ __forceinline__ float warpMax(float v) {
#pragma unroll
    for (int o = 16; o > 0; o >>= 1) v = fmaxf(v, __shfl_xor_sync(0xffffffffu, v, o));
    return v;
}
__device__ __forceinline__ float warpSum(float v) {
#pragma unroll
    for (int o = 16; o > 0; o >>= 1) v += __shfl_xor_sync(0xffffffffu, v, o);
    return v;
}
__global__ __launch_bounds__(256)
void rowstats(const float* __restrict__ attn, float2* __restrict__ stats)
{
    const int lane = threadIdx.x & 31, warp = threadIdx.x >> 5;
    const size_t row = (size_t)blockIdx.x * 8 + warp;
    const float4* p = (const float4*)(attn + row * (size_t)L_);

    float4 a[16];
#pragma unroll
    for (int i = 0; i < 16; i++) a[i] = p[lane + i * 32];

    float m = -3.4e38f;
#pragma unroll
    for (int i = 0; i < 16; i++)
        m = fmaxf(m, fmaxf(fmaxf(a[i].x, a[i].y), fmaxf(a[i].z, a[i].w)));
    m = warpMax(m);

    float s = 0.0f;
#pragma unroll
    for (int i = 0; i < 16; i++)
        s += __expf(a[i].x - m) + __expf(a[i].y - m) + __expf(a[i].z - m) + __expf(a[i].w - m);
    s = warpSum(s);

    if (lane == 0) stats[row] = make_float2(m, 1.0f / s);
}

// ---------------------------------------------------------------------------
// Fused softmax + AV. Per CTA: 128 q rows x full K=2048, 64 d outputs.
// Streams raw S tiles, converts to P = exp(S-m) (normalization deferred to
// epilogue), writes normalized P fp32 back in place, MMA on hi/lo halves.
// smem layout (bytes):
//  [0, 36864)       S fp32: 2 bufs x 128 x SRF floats
//  [36864, 47104)   Ah plane 128 x STR halfs
//  [47104, 57344)   Al plane
//  [57344, 77824)   V: 2 bufs x (Vh 64xSTR + Vl 64xSTR) halfs
//  [77824, 78848)   row stats float2[128]
// ---------------------------------------------------------------------------
#define AV_OFF_AH 36864
#define AV_OFF_AL 47104
#define AV_OFF_V  57344
#define AV_OFF_ST 77824
#define AV_SMEM   78848

__global__ __launch_bounds__(256) void av_fused(
    float* __restrict__ attn, const float2* __restrict__ stats)
{
    extern __shared__ char dsmc[];
    float*  Sbuf = (float*)dsmc;
    __half* Ahp  = (__half*)(dsmc + AV_OFF_AH);
    __half* Alp  = (__half*)(dsmc + AV_OFF_AL);
    float2* sst  = (float2*)(dsmc + AV_OFF_ST);

    const int tid = threadIdx.x, wid = tid >> 5, lane = tid & 31;
    const int wm = wid >> 2, wn = wid & 3;
    const int by = blockIdx.x, bh_ = blockIdx.y;
    const int b = bh_ >> 4, h = bh_ & 15;
    const uint32_t sb = smem_u32(dsmc);
    const uint32_t uAh = sb + AV_OFF_AH, uAl = sb + AV_OFF_AL, uV = sb + AV_OFF_V;

    const size_t pb = ((size_t)bh_ * L_ + by * 128) * L_;
    const size_t vbase = (size_t)bh_ * 64 * L_;

    if (tid < 128) sst[tid] = stats[(size_t)bh_ * L_ + by * 128 + tid];

    float acc[4][2][4];
#pragma unroll
    for (int i = 0; i < 4; i++)
#pragma unroll
        for (int j = 0; j < 2; j++)
#pragma unroll
            for (int f = 0; f < 4; f++) acc[i][j][f] = 0.0f;

    const int NT = L_ / 32;   // 64 slices
    const int c8 = tid & 7, r32 = tid >> 3;

    auto stage = [&](int kt, int buf) {
        const int k0 = kt * 32;
        for (int r = r32; r < 128; r += 32)
            cpa16(sb + (uint32_t)((buf * 128 + r) * SRF + c8 * 4) * 4,
                  attn + pb + (size_t)r * L_ + k0 + c8 * 4);
        cp_half32(g_Vth + vbase + k0, L_, uV + (uint32_t)buf * 10240, tid, 64);
        cp_half32(g_Vtl + vbase + k0, L_, uV + (uint32_t)buf * 10240 + 5120, tid, 64);
        CP_COMMIT();
    };

    stage(0, 0);
    stage(1, 1);

    for (int kt = 0; kt < NT; kt++) {
        if (kt + 1 < NT) { CP_WAIT1(); } else { CP_WAIT0(); }
        __syncthreads();
        const int buf = kt & 1;
        const int k0 = kt * 32;

        // conversion phase: exp, write normalized P back, build hi/lo planes
        for (int r = r32; r < 128; r += 32) {
            float4 v = *(const float4*)(Sbuf + (buf * 128 + r) * SRF + c8 * 4);
            float2 ms = sst[r];
            float p0 = __expf(v.x - ms.x);
            float p1 = __expf(v.y - ms.x);
            float p2 = __expf(v.z - ms.x);
            float p3 = __expf(v.w - ms.x);
            *(float4*)(attn + pb + (size_t)r * L_ + k0 + c8 * 4) =
                make_float4(p0 * ms.y, p1 * ms.y, p2 * ms.y, p3 * ms.y);
            uint32_t h0, l0, h1, l1;
            split2(p0, p1, h0, l0);
            split2(p2, p3, h1, l1);
            *(uint2*)(Ahp + r * STR + c8 * 4) = make_uint2(h0, h1);
            *(uint2*)(Alp + r * STR + c8 * 4) = make_uint2(l0, l1);
        }
        __syncthreads();

        // MMA phase
        const uint32_t pBh = uV + (uint32_t)buf * 10240;
        const uint32_t pBl = pBh + 5120;
#pragma unroll
        for (int ks = 0; ks < 32; ks += 16) {
            uint32_t ah[4][4], al[4][4], bh[2][2], bl[2][2];
            const uint32_t aoff = (uint32_t)((wm * 64 + (lane & 15)) * STR + ks + (lane >> 4) * 8) * 2;
            const uint32_t boff = (uint32_t)((wn * 16 + (lane & 7)) * STR + ks + ((lane >> 3) & 1) * 8) * 2;
#pragma unroll
            for (int mi = 0; mi < 4; mi++) {
                ldsm4(ah[mi], uAh + aoff + mi * 16 * STR * 2);
                ldsm4(al[mi], uAl + aoff + mi * 16 * STR * 2);
            }
#pragma unroll
            for (int ni = 0; ni < 2; ni++) {
                ldsm2(bh[ni], pBh + boff + ni * 8 * STR * 2);
                ldsm2(bl[ni], pBl + boff + ni * 8 * STR * 2);
            }
#pragma unroll
            for (int mi = 0; mi < 4; mi++)
#pragma unroll
                for (int ni = 0; ni < 2; ni++) {
                    mma16816(acc[mi][ni], ah[mi], bh[ni]);
                    mma16816(acc[mi][ni], ah[mi], bl[ni]);
                    mma16816(acc[mi][ni], al[mi], bh[ni]);
                }
        }
        __syncthreads();
        if (kt + 2 < NT) stage(kt + 2, buf);
    }

#pragma unroll
    for (int mi = 0; mi < 4; mi++)
#pragma unroll
        for (int ni = 0; ni < 2; ni++) {
            int rl = wm * 64 + mi * 16 + (lane >> 2);
            float is0 = sst[rl].y, is1 = sst[rl + 8].y;
            int tok = b * L_ + by * 128 + rl;
            int cc = h * 64 + wn * 16 + ni * 8 + (lane & 3) * 2;
            uint32_t hh, ll;
            split2(acc[mi][ni][0] * is0, acc[mi][ni][1] * is0, hh, ll);
            *(uint32_t*)(g_Ch + (size_t)tok * D_ + cc) = hh;
            *(uint32_t*)(g_Cl + (size_t)tok * D_ + cc) = ll;
            split2(acc[mi][ni][2] * is1, acc[mi][ni][3] * is1, hh, ll);
            *(uint32_t*)(g_Ch + (size_t)(tok + 8) * D_ + cc) = hh;
            *(uint32_t*)(g_Cl + (size_t)(tok + 8) * D_ + cc) = ll;
        }
}

// ---------------------------------------------------------------------------
extern "C" void kernel_launch(void* const* d_in, const int* in_sizes, int n_in,
                              void* d_out, int out_size)
{
    const float* query = (const float*)d_in[0];
    const float* key_  = (const float*)d_in[1];
    const float* value = (const float*)d_in[2];
    const float* Wq = (const float*)d_in[3];
    const float* bq = (const float*)d_in[4];
    const float* Wk = (const float*)d_in[5];
    const float* bk = (const float*)d_in[6];
    const float* Wv = (const float*)d_in[7];
    const float* bv = (const float*)d_in[8];
    const float* Wo = (const float*)d_in[9];
    const float* bo = (const float*)d_in[10];
    const float* rel_bias = (const float*)d_in[11];
    float* outp = (float*)d_out;

    static float *Vp = nullptr, *Ap = nullptr;
    static float2* Sp = nullptr;
    static __half *Wth = nullptr, *Wtl = nullptr, *Vth = nullptr, *Vtl = nullptr;
    static __half *Qh = nullptr, *Ql = nullptr, *Kh = nullptr, *Kl = nullptr;
    static __half *Ch = nullptr, *Cl = nullptr;
    if (!Vp) {
        cudaGetSymbolAddress((void**)&Vp, g_V);
        cudaGetSymbolAddress((void**)&Ap, g_attn);
        cudaGetSymbolAddress((void**)&Sp, g_stats);
        cudaGetSymbolAddress((void**)&Wth, g_Wth);
        cudaGetSymbolAddress((void**)&Wtl, g_Wtl);
        cudaGetSymbolAddress((void**)&Vth, g_Vth);
        cudaGetSymbolAddress((void**)&Vtl, g_Vtl);
        cudaGetSymbolAddress((void**)&Qh, g_Qh);
        cudaGetSymbolAddress((void**)&Ql, g_Ql);
        cudaGetSymbolAddress((void**)&Kh, g_Kh);
        cudaGetSymbolAddress((void**)&Kl, g_Kl);
        cudaGetSymbolAddress((void**)&Ch, g_Ch);
        cudaGetSymbolAddress((void**)&Cl, g_Cl);
        cudaFuncSetAttribute(proj_tc<0, 0>, cudaFuncAttributeMaxDynamicSharedMemorySize, PJ_SMEM);
        cudaFuncSetAttribute(proj_tc<0, 1>, cudaFuncAttributeMaxDynamicSharedMemorySize, PJ_SMEM);
        cudaFuncSetAttribute(proj_tc<1, 0>, cudaFuncAttributeMaxDynamicSharedMemorySize, PJ_SMEM);
        cudaFuncSetAttribute(scores_tc, cudaFuncAttributeMaxDynamicSharedMemorySize, SC_SMEM);
        cudaFuncSetAttribute(av_fused, cudaFuncAttributeMaxDynamicSharedMemorySize, AV_SMEM);
    }

    float* attn = ((size_t)out_size >= OUT_ELEMS + ATT_ELEMS) ? (outp + OUT_ELEMS) : Ap;
    const size_t WSZ = (size_t)D_ * D_;

    dim3 bT(32, 8);
    wsplit4<<<dim3(D_ / 32, D_ / 32, 4), bT>>>(Wq, Wk, Wv, Wo, Wth, Wtl);

    dim3 gProj(D_ / 128, BL_ / 128);   // (8, 32)
    proj_tc<0, 1><<<gProj, 256, PJ_SMEM>>>(query, nullptr, nullptr, Wth + 0 * WSZ, Wtl + 0 * WSZ,
                                           bq, nullptr, Qh, Ql);
    proj_tc<0, 1><<<gProj, 256, PJ_SMEM>>>(key_, nullptr, nullptr, Wth + 1 * WSZ, Wtl + 1 * WSZ,
                                           bk, nullptr, Kh, Kl);
    proj_tc<0, 0><<<gProj, 256, PJ_SMEM>>>(value, nullptr, nullptr, Wth + 2 * WSZ, Wtl + 2 * WSZ,
                                           bv, Vp, nullptr, nullptr);

    vsplit<<<dim3(D_ / 32, BL_ / 32), bT>>>(Vp, Vth, Vtl);

    dim3 gScores(L_ / 128, L_ / 128, B_ * H_);  // (16, 16, 32)
    scores_tc<<<gScores, 256, SC_SMEM>>>(rel_bias, attn);

    rowstats<<<(unsigned)(B_ * H_ * L_ / 8), 256>>>(attn, Sp);

    dim3 gAV(L_ / 128, B_ * H_);       // (16, 32)
    av_fused<<<gAV, 256, AV_SMEM>>>(attn, Sp);

    proj_tc<1, 0><<<gProj, 256, PJ_SMEM>>>(nullptr, Ch, Cl, Wth + 3 * WSZ, Wtl + 3 * WSZ,
                                           bo, outp, nullptr, nullptr);
}

// round 9
// speedup vs baseline: 2.0064x; 1.0328x over previous
#include <cuda_runtime.h>
#include <cuda_fp16.h>
#include <cstdint>
#include <cstddef>

#define B_   2
#define L_   2048
#define D_   1024
#define H_   16
#define HD_  64
#define BL_  (B_ * L_)
#define NBIAS_ 257
#define STR  40   // smem row stride (halfs) for 32-wide half tiles
#define STR2 72   // smem row stride (halfs) for 64-wide half tiles
#define SRF  36   // smem row stride (floats) for 32-wide fp32 tiles

static const size_t OUT_ELEMS = (size_t)BL_ * D_;
static const size_t ATT_ELEMS = (size_t)B_ * H_ * L_ * (size_t)L_;

// Device-global scratch (allocation-free rule)
__device__ float  g_V[(size_t)BL_ * D_];
__device__ __half g_Qh[(size_t)BL_ * D_], g_Ql[(size_t)BL_ * D_];
__device__ __half g_Kh[(size_t)BL_ * D_], g_Kl[(size_t)BL_ * D_];
__device__ __half g_Ch[(size_t)BL_ * D_], g_Cl[(size_t)BL_ * D_];
__device__ __half g_Wth[4ull * D_ * D_];
__device__ __half g_Wtl[4ull * D_ * D_];
__device__ __half g_Vth[(size_t)BL_ * D_]; // V transposed: [(b*16+h)*64+d][tok]
__device__ __half g_Vtl[(size_t)BL_ * D_];
__device__ float2 g_stats[(size_t)B_ * H_ * L_];   // per-row (max, 1/sum)
__device__ float  g_attn[(size_t)B_ * H_ * L_ * (size_t)L_]; // fallback

// ---------------------------------------------------------------------------
// Helpers
// ---------------------------------------------------------------------------
__device__ __forceinline__ uint32_t smem_u32(const void* p) {
    uint32_t a;
    asm("{ .reg .u64 t; cvta.to.shared.u64 t, %1; cvt.u32.u64 %0, t; }" : "=r"(a) : "l"(p));
    return a;
}
__device__ __forceinline__ void cpa16(uint32_t d, const void* s) {
    asm volatile("cp.async.cg.shared.global [%0], [%1], 16;" :: "r"(d), "l"(s));
}
#define CP_COMMIT() asm volatile("cp.async.commit_group;" ::: "memory")
#define CP_WAIT0()  asm volatile("cp.async.wait_group 0;" ::: "memory")
#define CP_WAIT1()  asm volatile("cp.async.wait_group 1;" ::: "memory")

__device__ __forceinline__ void ldsm4(uint32_t r[4], uint32_t addr) {
    asm volatile("ldmatrix.sync.aligned.m8n8.x4.shared.b16 {%0,%1,%2,%3}, [%4];"
                 : "=r"(r[0]), "=r"(r[1]), "=r"(r[2]), "=r"(r[3]) : "r"(addr));
}
__device__ __forceinline__ void ldsm2(uint32_t r[2], uint32_t addr) {
    asm volatile("ldmatrix.sync.aligned.m8n8.x2.shared.b16 {%0,%1}, [%2];"
                 : "=r"(r[0]), "=r"(r[1]) : "r"(addr));
}
__device__ __forceinline__ void mma16816(float c[4], const uint32_t a[4], const uint32_t b[2]) {
    asm volatile("mma.sync.aligned.m16n8k16.row.col.f32.f16.f16.f32 "
                 "{%0,%1,%2,%3}, {%4,%5,%6,%7}, {%8,%9}, {%0,%1,%2,%3};"
                 : "+f"(c[0]), "+f"(c[1]), "+f"(c[2]), "+f"(c[3])
                 : "r"(a[0]), "r"(a[1]), "r"(a[2]), "r"(a[3]), "r"(b[0]), "r"(b[1]));
}

__device__ __forceinline__ uint32_t h2u(__half2 v) { return *reinterpret_cast<uint32_t*>(&v); }

__device__ __forceinline__ void split2(float x, float y, uint32_t& hi, uint32_t& lo) {
    __half h0 = __float2half_rn(x), h1 = __float2half_rn(y);
    __half l0 = __float2half_rn(x - __half2float(h0));
    __half l1 = __float2half_rn(y - __half2float(h1));
    hi = h2u(__halves2half2(h0, h1));
    lo = h2u(__halves2half2(l0, l1));
}

// Async copy of half tile [rows][32] (gs = global row stride, halfs)
__device__ __forceinline__ void cp_half32(const __half* __restrict__ g, int gs,
                                          uint32_t sm, int tid, int rows) {
    int c = tid & 3, r0 = tid >> 2;
    for (int r = r0; r < rows; r += 64)
        cpa16(sm + (uint32_t)(r * STR + c * 8) * 2, g + (size_t)r * gs + c * 8);
}
// Async copy of half tile [rows][64], stride STR2
__device__ __forceinline__ void cp_half64(const __half* __restrict__ g, int gs,
                                          uint32_t sm, int tid, int rows) {
    int c = tid & 7, r0 = tid >> 3;
    for (int r = r0; r < rows; r += 32)
        cpa16(sm + (uint32_t)(r * STR2 + c * 8) * 2, g + (size_t)r * gs + c * 8);
}
// Synchronous fp32->hi/lo split tile loader [rows][32]
__device__ __forceinline__ void ld_splitA(const float* __restrict__ g, int gs,
                                          __half* __restrict__ sh, __half* __restrict__ sl,
                                          int tid, int rows) {
    int c = tid & 7, r0 = tid >> 3;
    for (int r = r0; r < rows; r += 32) {
        float4 v = *(const float4*)(g + (size_t)r * gs + c * 4);
        uint32_t h0, l0, h1, l1;
        split2(v.x, v.y, h0, l0);
        split2(v.z, v.w, h1, l1);
        *(uint2*)(sh + r * STR + c * 4) = make_uint2(h0, h1);
        *(uint2*)(sl + r * STR + c * 4) = make_uint2(l0, l1);
    }
}

// ---------------------------------------------------------------------------
// Prep kernels
// ---------------------------------------------------------------------------
__global__ void wsplit4(const float* __restrict__ W0, const float* __restrict__ W1,
                        const float* __restrict__ W2, const float* __restrict__ W3,
                        __half* __restrict__ Th, __half* __restrict__ Tl) {
    __shared__ float t[32][33];
    const float* Ws[4] = {W0, W1, W2, W3};
    const float* W = Ws[blockIdx.z];
    __half* th = Th + (size_t)blockIdx.z * D_ * D_;
    __half* tl = Tl + (size_t)blockIdx.z * D_ * D_;
    int bx = blockIdx.x * 32, by = blockIdx.y * 32;
    int tx = threadIdx.x, ty = threadIdx.y;
    for (int i = ty; i < 32; i += 8)
        t[i][tx] = W[(size_t)(by + i) * D_ + bx + tx];
    __syncthreads();
    for (int i = ty; i < 32; i += 8) {
        float v = t[tx][i];
        __half h = __float2half_rn(v);
        th[(size_t)(bx + i) * D_ + by + tx] = h;
        tl[(size_t)(bx + i) * D_ + by + tx] = __float2half_rn(v - __half2float(h));
    }
}
__global__ void vsplit(const float* __restrict__ V, __half* __restrict__ Th,
                       __half* __restrict__ Tl) {
    __shared__ float t[32][33];
    int bx = blockIdx.x * 32, by = blockIdx.y * 32;
    int tx = threadIdx.x, ty = threadIdx.y;
    for (int i = ty; i < 32; i += 8)
        t[i][tx] = V[(size_t)(by + i) * D_ + bx + tx];
    __syncthreads();
    int tok = by + tx;
    int b = tok >> 11, tokin = tok & (L_ - 1);
    for (int i = ty; i < 32; i += 8) {
        int f = bx + i;
        float v = t[tx][i];
        size_t row = ((size_t)(b * H_ + (f >> 6))) * 64 + (f & 63);
        __half h = __float2half_rn(v);
        Th[row * L_ + tokin] = h;
        Tl[row * L_ + tokin] = __float2half_rn(v - __half2float(h));
    }
}

// ---------------------------------------------------------------------------
// Shared MMA block helpers (term-major issue order: all independent-acc MMAs
// of one split term before the next term touches the same accumulator)
// ---------------------------------------------------------------------------
#define PJ_PL   (128 * STR)
#define PJ_BUF  (4 * PJ_PL)
#define PJ_SMEM (2 * PJ_BUF * 2)

template <int NI>
__device__ __forceinline__ void mma_block(
    float acc[4][NI][4], const uint32_t pAh, const uint32_t pAl,
    const uint32_t pBh, const uint32_t pBl,
    int wm, int wn, int lane, int nW)
{
#pragma unroll
    for (int ks = 0; ks < 32; ks += 16) {
        uint32_t ah[4][4], al[4][4], bh[NI][2], bl[NI][2];
        const uint32_t aoff = (uint32_t)((wm * 64 + (lane & 15)) * STR + ks + (lane >> 4) * 8) * 2;
        const uint32_t boff = (uint32_t)((wn * (8 * NI) + (lane & 7)) * STR + ks + ((lane >> 3) & 1) * 8) * 2;
#pragma unroll
        for (int mi = 0; mi < 4; mi++) {
            ldsm4(ah[mi], pAh + aoff + mi * 16 * STR * 2);
            ldsm4(al[mi], pAl + aoff + mi * 16 * STR * 2);
        }
#pragma unroll
        for (int ni = 0; ni < NI; ni++) {
            ldsm2(bh[ni], pBh + boff + ni * 8 * STR * 2);
            ldsm2(bl[ni], pBl + boff + ni * 8 * STR * 2);
        }
        // term-major: maximize distance between writes to the same acc
#pragma unroll
        for (int mi = 0; mi < 4; mi++)
#pragma unroll
            for (int ni = 0; ni < NI; ni++) mma16816(acc[mi][ni], ah[mi], bh[ni]);
#pragma unroll
        for (int mi = 0; mi < 4; mi++)
#pragma unroll
            for (int ni = 0; ni < NI; ni++) mma16816(acc[mi][ni], ah[mi], bl[ni]);
#pragma unroll
        for (int mi = 0; mi < 4; mi++)
#pragma unroll
            for (int ni = 0; ni < NI; ni++) mma16816(acc[mi][ni], al[mi], bh[ni]);
    }
}

// ---------------------------------------------------------------------------
// Merged Q/K/V projection: grid (8, 32, 3). z picks input/weight/output.
// ---------------------------------------------------------------------------
__global__ __launch_bounds__(256) void qkv_proj(
    const float* __restrict__ query, const float* __restrict__ key_,
    const float* __restrict__ value,
    const __half* __restrict__ Wth, const __half* __restrict__ Wtl,
    const float* __restrict__ bq, const float* __restrict__ bk,
    const float* __restrict__ bv,
    __half* __restrict__ Qh, __half* __restrict__ Ql,
    __half* __restrict__ Kh, __half* __restrict__ Kl,
    float* __restrict__ Vp)
{
    extern __shared__ __half dsm[];
    const int tid = threadIdx.x, wid = tid >> 5, lane = tid & 31;
    const int wm = wid >> 2, wn = wid & 3;
    const int n0 = blockIdx.x * 128, m0 = blockIdx.y * 128;
    const int z = blockIdx.z;
    const uint32_t sb = smem_u32(dsm);

    const float* A32 = (z == 0) ? query : (z == 1) ? key_ : value;
    const __half* Bth = Wth + (size_t)z * D_ * D_;
    const __half* Btl = Wtl + (size_t)z * D_ * D_;
    const float* bias = (z == 0) ? bq : (z == 1) ? bk : bv;

    float acc[4][4][4];
#pragma unroll
    for (int i = 0; i < 4; i++)
#pragma unroll
        for (int j = 0; j < 4; j++)
#pragma unroll
            for (int f = 0; f < 4; f++) acc[i][j][f] = 0.0f;

    const int NT = D_ / 32;

    auto stage = [&](int kt, int buf) {
        const int k0 = kt * 32;
        __half* base = dsm + buf * PJ_BUF;
        uint32_t ub = sb + (uint32_t)(buf * PJ_BUF) * 2;
        cp_half32(Bth + (size_t)n0 * D_ + k0, D_, ub + 2 * PJ_PL * 2, tid, 128);
        cp_half32(Btl + (size_t)n0 * D_ + k0, D_, ub + 3 * PJ_PL * 2, tid, 128);
        CP_COMMIT();
        ld_splitA(A32 + (size_t)m0 * D_ + k0, D_, base + 0 * PJ_PL, base + 1 * PJ_PL, tid, 128);
    };

    stage(0, 0);
    stage(1, 1);

    for (int kt = 0; kt < NT; kt++) {
        if (kt + 1 < NT) { CP_WAIT1(); } else { CP_WAIT0(); }
        __syncthreads();
        const int buf = kt & 1;
        mma_block<4>(acc,
                     sb + (uint32_t)(buf * PJ_BUF + 0 * PJ_PL) * 2,
                     sb + (uint32_t)(buf * PJ_BUF + 1 * PJ_PL) * 2,
                     sb + (uint32_t)(buf * PJ_BUF + 2 * PJ_PL) * 2,
                     sb + (uint32_t)(buf * PJ_BUF + 3 * PJ_PL) * 2,
                     wm, wn, lane, 4);
        __syncthreads();
        if (kt + 2 < NT) stage(kt + 2, buf);
    }

#pragma unroll
    for (int mi = 0; mi < 4; mi++)
#pragma unroll
        for (int ni = 0; ni < 4; ni++) {
            int r = m0 + wm * 64 + mi * 16 + (lane >> 2);
            int cc = n0 + wn * 32 + ni * 8 + (lane & 3) * 2;
            float b0 = bias[cc], b1 = bias[cc + 1];
            float v0 = acc[mi][ni][0] + b0, v1 = acc[mi][ni][1] + b1;
            float v2 = acc[mi][ni][2] + b0, v3 = acc[mi][ni][3] + b1;
            if (z == 2) {
                *(float2*)(Vp + (size_t)r * D_ + cc) = make_float2(v0, v1);
                *(float2*)(Vp + (size_t)(r + 8) * D_ + cc) = make_float2(v2, v3);
            } else {
                __half* Ch = (z == 0) ? Qh : Kh;
                __half* Cl = (z == 0) ? Ql : Kl;
                uint32_t h, l;
                split2(v0, v1, h, l);
                *(uint32_t*)(Ch + (size_t)r * D_ + cc) = h;
                *(uint32_t*)(Cl + (size_t)r * D_ + cc) = l;
                split2(v2, v3, h, l);
                *(uint32_t*)(Ch + (size_t)(r + 8) * D_ + cc) = h;
                *(uint32_t*)(Cl + (size_t)(r + 8) * D_ + cc) = l;
            }
        }
}

// ---------------------------------------------------------------------------
// Output projection: ctx halves @ Wo + bo -> fp32 out.
// ---------------------------------------------------------------------------
__global__ __launch_bounds__(256) void out_proj(
    const __half* __restrict__ Ahg, const __half* __restrict__ Alg,
    const __half* __restrict__ Bth, const __half* __restrict__ Btl,
    const float* __restrict__ bias, float* __restrict__ C32)
{
    extern __shared__ __half dsm[];
    const int tid = threadIdx.x, wid = tid >> 5, lane = tid & 31;
    const int wm = wid >> 2, wn = wid & 3;
    const int n0 = blockIdx.x * 128, m0 = blockIdx.y * 128;
    const uint32_t sb = smem_u32(dsm);

    float acc[4][4][4];
#pragma unroll
    for (int i = 0; i < 4; i++)
#pragma unroll
        for (int j = 0; j < 4; j++)
#pragma unroll
            for (int f = 0; f < 4; f++) acc[i][j][f] = 0.0f;

    const int NT = D_ / 32;

    auto stage = [&](int kt, int buf) {
        const int k0 = kt * 32;
        uint32_t ub = sb + (uint32_t)(buf * PJ_BUF) * 2;
        cp_half32(Ahg + (size_t)m0 * D_ + k0, D_, ub + 0 * PJ_PL * 2, tid, 128);
        cp_half32(Alg + (size_t)m0 * D_ + k0, D_, ub + 1 * PJ_PL * 2, tid, 128);
        cp_half32(Bth + (size_t)n0 * D_ + k0, D_, ub + 2 * PJ_PL * 2, tid, 128);
        cp_half32(Btl + (size_t)n0 * D_ + k0, D_, ub + 3 * PJ_PL * 2, tid, 128);
        CP_COMMIT();
    };

    stage(0, 0);
    stage(1, 1);

    for (int kt = 0; kt < NT; kt++) {
        if (kt + 1 < NT) { CP_WAIT1(); } else { CP_WAIT0(); }
        __syncthreads();
        const int buf = kt & 1;
        mma_block<4>(acc,
                     sb + (uint32_t)(buf * PJ_BUF + 0 * PJ_PL) * 2,
                     sb + (uint32_t)(buf * PJ_BUF + 1 * PJ_PL) * 2,
                     sb + (uint32_t)(buf * PJ_BUF + 2 * PJ_PL) * 2,
                     sb + (uint32_t)(buf * PJ_BUF + 3 * PJ_PL) * 2,
                     wm, wn, lane, 4);
        __syncthreads();
        if (kt + 2 < NT) stage(kt + 2, buf);
    }

#pragma unroll
    for (int mi = 0; mi < 4; mi++)
#pragma unroll
        for (int ni = 0; ni < 4; ni++) {
            int r = m0 + wm * 64 + mi * 16 + (lane >> 2);
            int cc = n0 + wn * 32 + ni * 8 + (lane & 3) * 2;
            float b0 = bias[cc], b1 = bias[cc + 1];
            *(float2*)(C32 + (size_t)r * D_ + cc) =
                make_float2(acc[mi][ni][0] + b0, acc[mi][ni][1] + b1);
            *(float2*)(C32 + (size_t)(r + 8) * D_ + cc) =
                make_float2(acc[mi][ni][2] + b0, acc[mi][ni][3] + b1);
        }
}

// ---------------------------------------------------------------------------
// Scores: whole K=64 resident; term-major MMA order.
// ---------------------------------------------------------------------------
#define SC_PL   (128 * STR2)
#define SC_SMEM (4 * SC_PL * 2)

__global__ __launch_bounds__(256) void scores_tc(
    const float* __restrict__ rel_bias, float* __restrict__ attn)
{
    extern __shared__ __half dsm[];
    __shared__ float sbias[NBIAS_];

    const int tid = threadIdx.x, wid = tid >> 5, lane = tid & 31;
    const int wm = wid >> 2, wn = wid & 3;
    const int bx = blockIdx.x, by = blockIdx.y, bh_ = blockIdx.z;
    const int b = bh_ >> 4, h = bh_ & 15;
    const uint32_t sb = smem_u32(dsm);

    const size_t qb = (size_t)(b * L_ + by * 128) * D_ + h * HD_;
    const size_t kb = (size_t)(b * L_ + bx * 128) * D_ + h * HD_;

    cp_half64(g_Qh + qb, D_, sb + 0u * SC_PL * 2, tid, 128);
    cp_half64(g_Ql + qb, D_, sb + 1u * SC_PL * 2, tid, 128);
    cp_half64(g_Kh + kb, D_, sb + 2u * SC_PL * 2, tid, 128);
    cp_half64(g_Kl + kb, D_, sb + 3u * SC_PL * 2, tid, 128);
    CP_COMMIT();

    for (int i = tid; i < NBIAS_; i += 256) sbias[i] = rel_bias[i * H_ + h];

    float acc[4][4][4];
#pragma unroll
    for (int i = 0; i < 4; i++)
#pragma unroll
        for (int j = 0; j < 4; j++)
#pragma unroll
            for (int f = 0; f < 4; f++) acc[i][j][f] = 0.0f;

    CP_WAIT0();
    __syncthreads();

    const uint32_t pAh = sb + 0u * SC_PL * 2, pAl = sb + 1u * SC_PL * 2;
    const uint32_t pBh = sb + 2u * SC_PL * 2, pBl = sb + 3u * SC_PL * 2;
#pragma unroll
    for (int ks = 0; ks < 64; ks += 16) {
        uint32_t ah[4][4], al[4][4], bh[4][2], bl[4][2];
        const uint32_t aoff = (uint32_t)((wm * 64 + (lane & 15)) * STR2 + ks + (lane >> 4) * 8) * 2;
        const uint32_t boff = (uint32_t)((wn * 32 + (lane & 7)) * STR2 + ks + ((lane >> 3) & 1) * 8) * 2;
#pragma unroll
        for (int mi = 0; mi < 4; mi++) {
            ldsm4(ah[mi], pAh + aoff + mi * 16 * STR2 * 2);
            ldsm4(al[mi], pAl + aoff + mi * 16 * STR2 * 2);
        }
#pragma unroll
        for (int ni = 0; ni < 4; ni++) {
            ldsm2(bh[ni], pBh + boff + ni * 8 * STR2 * 2);
            ldsm2(bl[ni], pBl + boff + ni * 8 * STR2 * 2);
        }
#pragma unroll
        for (int mi = 0; mi < 4; mi++)
#pragma unroll
            for (int ni = 0; ni < 4; ni++) mma16816(acc[mi][ni], ah[mi], bh[ni]);
#pragma unroll
        for (int mi = 0; mi < 4; mi++)
#pragma unroll
            for (int ni = 0; ni < 4; ni++) mma16816(acc[mi][ni], ah[mi], bl[ni]);
#pragma unroll
        for (int mi = 0; mi < 4; mi++)
#pragma unroll
            for (int ni = 0; ni < 4; ni++) mma16816(acc[mi][ni], al[mi], bh[ni]);
    }

    float* base = attn + (size_t)bh_ * L_ * L_;
#pragma unroll
    for (int mi = 0; mi < 4; mi++)
#pragma unroll
        for (int ni = 0; ni < 4; ni++) {
            int q0 = by * 128 + wm * 64 + mi * 16 + (lane >> 2);
            int kc = bx * 128 + wn * 32 + ni * 8 + (lane & 3) * 2;
#pragma unroll
            for (int half_ = 0; half_ < 2; half_++) {
                int q = q0 + half_ * 8;
                int rel0 = kc - q;     rel0 = rel0 < -128 ? -128 : (rel0 > 128 ? 128 : rel0);
                int rel1 = kc + 1 - q; rel1 = rel1 < -128 ? -128 : (rel1 > 128 ? 128 : rel1);
                float2 o = make_float2(
                    acc[mi][ni][half_ * 2 + 0] * 0.125f + sbias[rel0 + 128],
                    acc[mi][ni][half_ * 2 + 1] * 0.125f + sbias[rel1 + 128]);
                *(float2*)(base + (size_t)q * L_ + kc) = o;
            }
        }
}

// ---------------------------------------------------------------------------
// Row stats
// ---------------------------------------------------------------------------
__device__ __forceinline__ float warpMax(float v) {
#pragma unroll
    for (int o = 16; o > 0; o >>= 1) v = fmaxf(v, __shfl_xor_sync(0xffffffffu, v, o));
    return v;
}
__device__ __forceinline__ float warpSum(float v) {
#pragma unroll
    for (int o = 16; o > 0; o >>= 1) v += __shfl_xor_sync(0xffffffffu, v, o);
    return v;
}
__global__ __launch_bounds__(256)
void rowstats(const float* __restrict__ attn, float2* __restrict__ stats)
{
    const int lane = threadIdx.x & 31, warp = threadIdx.x >> 5;
    const size_t row = (size_t)blockIdx.x * 8 + warp;
    const float4* p = (const float4*)(attn + row * (size_t)L_);

    float4 a[16];
#pragma unroll
    for (int i = 0; i < 16; i++) a[i] = p[lane + i * 32];

    float m = -3.4e38f;
#pragma unroll
    for (int i = 0; i < 16; i++)
        m = fmaxf(m, fmaxf(fmaxf(a[i].x, a[i].y), fmaxf(a[i].z, a[i].w)));
    m = warpMax(m);

    float s = 0.0f;
#pragma unroll
    for (int i = 0; i < 16; i++)
        s += __expf(a[i].x - m) + __expf(a[i].y - m) + __expf(a[i].z - m) + __expf(a[i].w - m);
    s = warpSum(s);

    if (lane == 0) stats[row] = make_float2(m, 1.0f / s);
}

// ---------------------------------------------------------------------------
// Fused softmax + AV (term-major MMA order).
// ---------------------------------------------------------------------------
#define AV_OFF_AH 36864
#define AV_OFF_AL 47104
#define AV_OFF_V  57344
#define AV_OFF_ST 77824
#define AV_SMEM   78848

__global__ __launch_bounds__(256) void av_fused(
    float* __restrict__ attn, const float2* __restrict__ stats)
{
    extern __shared__ char dsmc[];
    float*  Sbuf = (float*)dsmc;
    __half* Ahp  = (__half*)(dsmc + AV_OFF_AH);
    __half* Alp  = (__half*)(dsmc + AV_OFF_AL);
    float2* sst  = (float2*)(dsmc + AV_OFF_ST);

    const int tid = threadIdx.x, wid = tid >> 5, lane = tid & 31;
    const int wm = wid >> 2, wn = wid & 3;
    const int by = blockIdx.x, bh_ = blockIdx.y;
    const int b = bh_ >> 4, h = bh_ & 15;
    const uint32_t sb = smem_u32(dsmc);
    const uint32_t uAh = sb + AV_OFF_AH, uAl = sb + AV_OFF_AL, uV = sb + AV_OFF_V;

    const size_t pb = ((size_t)bh_ * L_ + by * 128) * L_;
    const size_t vbase = (size_t)bh_ * 64 * L_;

    if (tid < 128) sst[tid] = stats[(size_t)bh_ * L_ + by * 128 + tid];

    float acc[4][2][4];
#pragma unroll
    for (int i = 0; i < 4; i++)
#pragma unroll
        for (int j = 0; j < 2; j++)
#pragma unroll
            for (int f = 0; f < 4; f++) acc[i][j][f] = 0.0f;

    const int NT = L_ / 32;
    const int c8 = tid & 7, r32 = tid >> 3;

    auto stage = [&](int kt, int buf) {
        const int k0 = kt * 32;
        for (int r = r32; r < 128; r += 32)
            cpa16(sb + (uint32_t)((buf * 128 + r) * SRF + c8 * 4) * 4,
                  attn + pb + (size_t)r * L_ + k0 + c8 * 4);
        cp_half32(g_Vth + vbase + k0, L_, uV + (uint32_t)buf * 10240, tid, 64);
        cp_half32(g_Vtl + vbase + k0, L_, uV + (uint32_t)buf * 10240 + 5120, tid, 64);
        CP_COMMIT();
    };

    stage(0, 0);
    stage(1, 1);

    for (int kt = 0; kt < NT; kt++) {
        if (kt + 1 < NT) { CP_WAIT1(); } else { CP_WAIT0(); }
        __syncthreads();
        const int buf = kt & 1;
        const int k0 = kt * 32;

        for (int r = r32; r < 128; r += 32) {
            float4 v = *(const float4*)(Sbuf + (buf * 128 + r) * SRF + c8 * 4);
            float2 ms = sst[r];
            float p0 = __expf(v.x - ms.x);
            float p1 = __expf(v.y - ms.x);
            float p2 = __expf(v.z - ms.x);
            float p3 = __expf(v.w - ms.x);
            *(float4*)(attn + pb + (size_t)r * L_ + k0 + c8 * 4) =
                make_float4(p0 * ms.y, p1 * ms.y, p2 * ms.y, p3 * ms.y);
            uint32_t h0, l0, h1, l1;
            split2(p0, p1, h0, l0);
            split2(p2, p3, h1, l1);
            *(uint2*)(Ahp + r * STR + c8 * 4) = make_uint2(h0, h1);
            *(uint2*)(Alp + r * STR + c8 * 4) = make_uint2(l0, l1);
        }
        __syncthreads();

        const uint32_t pBh = uV + (uint32_t)buf * 10240;
        const uint32_t pBl = pBh + 5120;
        mma_block<2>(acc, uAh, uAl, pBh, pBl, wm, wn, lane, 2);
        __syncthreads();
        if (kt + 2 < NT) stage(kt + 2, buf);
    }

#pragma unroll
    for (int mi = 0; mi < 4; mi++)
#pragma unroll
        for (int ni = 0; ni < 2; ni++) {
            int rl = wm * 64 + mi * 16 + (lane >> 2);
            float is0 = sst[rl].y, is1 = sst[rl + 8].y;
            int tok = b * L_ + by * 128 + rl;
            int cc = h * 64 + wn * 16 + ni * 8 + (lane & 3) * 2;
            uint32_t hh, ll;
            split2(acc[mi][ni][0] * is0, acc[mi][ni][1] * is0, hh, ll);
            *(uint32_t*)(g_Ch + (size_t)tok * D_ + cc) = hh;
            *(uint32_t*)(g_Cl + (size_t)tok * D_ + cc) = ll;
            split2(acc[mi][ni][2] * is1, acc[mi][ni][3] * is1, hh, ll);
            *(uint32_t*)(g_Ch + (size_t)(tok + 8) * D_ + cc) = hh;
            *(uint32_t*)(g_Cl + (size_t)(tok + 8) * D_ + cc) = ll;
        }
}

// ---------------------------------------------------------------------------
extern "C" void kernel_launch(void* const* d_in, const int* in_sizes, int n_in,
                              void* d_out, int out_size)
{
    const float* query = (const float*)d_in[0];
    const float* key_  = (const float*)d_in[1];
    const float* value = (const float*)d_in[2];
    const float* Wq = (const float*)d_in[3];
    const float* bq = (const float*)d_in[4];
    const float* Wk = (const float*)d_in[5];
    const float* bk = (const float*)d_in[6];
    const float* Wv = (const float*)d_in[7];
    const float* bv = (const float*)d_in[8];
    const float* Wo = (const float*)d_in[9];
    const float* bo = (const float*)d_in[10];
    const float* rel_bias = (const float*)d_in[11];
    float* outp = (float*)d_out;

    static float *Vp = nullptr, *Ap = nullptr;
    static float2* Sp = nullptr;
    static __half *Wth = nullptr, *Wtl = nullptr, *Vth = nullptr, *Vtl = nullptr;
    static __half *Qh = nullptr, *Ql = nullptr, *Kh = nullptr, *Kl = nullptr;
    static __half *Ch = nullptr, *Cl = nullptr;
    if (!Vp) {
        cudaGetSymbolAddress((void**)&Vp, g_V);
        cudaGetSymbolAddress((void**)&Ap, g_attn);
        cudaGetSymbolAddress((void**)&Sp, g_stats);
        cudaGetSymbolAddress((void**)&Wth, g_Wth);
        cudaGetSymbolAddress((void**)&Wtl, g_Wtl);
        cudaGetSymbolAddress((void**)&Vth, g_Vth);
        cudaGetSymbolAddress((void**)&Vtl, g_Vtl);
        cudaGetSymbolAddress((void**)&Qh, g_Qh);
        cudaGetSymbolAddress((void**)&Ql, g_Ql);
        cudaGetSymbolAddress((void**)&Kh, g_Kh);
        cudaGetSymbolAddress((void**)&Kl, g_Kl);
        cudaGetSymbolAddress((void**)&Ch, g_Ch);
        cudaGetSymbolAddress((void**)&Cl, g_Cl);
        cudaFuncSetAttribute(qkv_proj, cudaFuncAttributeMaxDynamicSharedMemorySize, PJ_SMEM);
        cudaFuncSetAttribute(out_proj, cudaFuncAttributeMaxDynamicSharedMemorySize, PJ_SMEM);
        cudaFuncSetAttribute(scores_tc, cudaFuncAttributeMaxDynamicSharedMemorySize, SC_SMEM);
        cudaFuncSetAttribute(av_fused, cudaFuncAttributeMaxDynamicSharedMemorySize, AV_SMEM);
    }

    float* attn = ((size_t)out_size >= OUT_ELEMS + ATT_ELEMS) ? (outp + OUT_ELEMS) : Ap;
    const size_t WSZ = (size_t)D_ * D_;

    dim3 bT(32, 8);
    wsplit4<<<dim3(D_ / 32, D_ / 32, 4), bT>>>(Wq, Wk, Wv, Wo, Wth, Wtl);

    dim3 gQKV(D_ / 128, BL_ / 128, 3);   // (8, 32, 3)
    qkv_proj<<<gQKV, 256, PJ_SMEM>>>(query, key_, value, Wth, Wtl,
                                     bq, bk, bv, Qh, Ql, Kh, Kl, Vp);

    vsplit<<<dim3(D_ / 32, BL_ / 32), bT>>>(Vp, Vth, Vtl);

    dim3 gScores(L_ / 128, L_ / 128, B_ * H_);  // (16, 16, 32)
    scores_tc<<<gScores, 256, SC_SMEM>>>(rel_bias, attn);

    rowstats<<<(unsigned)(B_ * H_ * L_ / 8), 256>>>(attn, Sp);

    dim3 gAV(L_ / 128, B_ * H_);       // (16, 32)
    av_fused<<<gAV, 256, AV_SMEM>>>(attn, Sp);

    out_proj<<<dim3(D_ / 128, BL_ / 128), 256, PJ_SMEM>>>(Ch, Cl, Wth + 3 * WSZ, Wtl + 3 * WSZ,
                                                          bo, outp);
}